// round 6
// baseline (speedup 1.0000x reference)
#include <cuda_runtime.h>
#include <math.h>

#define BB 2
#define TT 2048
#define CC 1024
#define HH 16
#define DHD 64
#define MTOT (BB*TT)
#define SPAD 65
#define VPAD 68   // multiple of 4 -> float4-aligned shared stores

// scratch (no allocation allowed)
__device__ float g_q[MTOT * CC];
__device__ float g_k[MTOT * CC];
__device__ float g_v[MTOT * CC];
__device__ float g_att[MTOT * CC];

// ---------------------------------------------------------------------------
// NT GEMM: out[m,n] = sum_k A[m,k] * W[n,k] + bias[n]
// 128x128 tile, BK=8, 256 threads, 8x8 per thread.
// ---------------------------------------------------------------------------
__global__ __launch_bounds__(256) void gemm_nt(const float* __restrict__ A,
                                               const float* __restrict__ W,
                                               const float* __restrict__ bias,
                                               float* __restrict__ out,
                                               int M, int N, int K) {
    __shared__ float As[8][128];
    __shared__ float Bs[8][128];
    const int tid = threadIdx.x;
    const int tx = tid & 15, ty = tid >> 4;
    const int m0 = blockIdx.y * 128, n0 = blockIdx.x * 128;

    float acc[8][8];
#pragma unroll
    for (int i = 0; i < 8; i++)
#pragma unroll
        for (int j = 0; j < 8; j++) acc[i][j] = 0.f;

    const int lrow = tid >> 1;          // 0..127
    const int lkv = (tid & 1) * 4;      // 0 or 4

    for (int k0 = 0; k0 < K; k0 += 8) {
        float4 av = *(const float4*)&A[(size_t)(m0 + lrow) * K + k0 + lkv];
        float4 bv = *(const float4*)&W[(size_t)(n0 + lrow) * K + k0 + lkv];
        As[lkv + 0][lrow] = av.x; As[lkv + 1][lrow] = av.y;
        As[lkv + 2][lrow] = av.z; As[lkv + 3][lrow] = av.w;
        Bs[lkv + 0][lrow] = bv.x; Bs[lkv + 1][lrow] = bv.y;
        Bs[lkv + 2][lrow] = bv.z; Bs[lkv + 3][lrow] = bv.w;
        __syncthreads();
#pragma unroll
        for (int kk = 0; kk < 8; kk++) {
            float a[8], b[8];
#pragma unroll
            for (int i = 0; i < 8; i++) a[i] = As[kk][ty + 16 * i];
#pragma unroll
            for (int j = 0; j < 8; j++) b[j] = Bs[kk][tx + 16 * j];
#pragma unroll
            for (int i = 0; i < 8; i++)
#pragma unroll
                for (int j = 0; j < 8; j++) acc[i][j] += a[i] * b[j];
        }
        __syncthreads();
    }

#pragma unroll
    for (int j = 0; j < 8; j++) {
        float bv = bias[n0 + tx + 16 * j];
#pragma unroll
        for (int i = 0; i < 8; i++)
            out[(size_t)(m0 + ty + 16 * i) * N + n0 + tx + 16 * j] = acc[i][j] + bv;
    }
}

// ---------------------------------------------------------------------------
// Flash attention: one CTA per (q-tile of 64, b*h). BN=64 key tiles, online
// softmax, key mask from x[:, :, 0] != 0.
// Thread layout 16x16, each thread: 4 q-rows x 4 cols.
// Dynamic smem: Qs[64][SPAD] (k-major), KP[64][SPAD] (Ks k-major / Ps row-major),
//               Vs[64][VPAD] (row-major, VPAD=68 for aligned float4 stores).
// ---------------------------------------------------------------------------
__global__ __launch_bounds__(256) void attn_kernel(const float* __restrict__ x,
                                                   float* __restrict__ attout) {
    extern __shared__ float sm[];
    float* Qs = sm;                   // Qs[d*SPAD + r]
    float* KP = sm + 64 * SPAD;       // Ks[d*SPAD + c]  then  Ps[r*SPAD + c]
    float* Vs = sm + 2 * 64 * SPAD;   // Vs[c*VPAD + d]
    __shared__ float kval[64];

    const int tid = threadIdx.x;
    const int tx = tid & 15, ty = tid >> 4;
    const int bh = blockIdx.y;
    const int b = bh / HH, h = bh % HH;
    const int q0 = blockIdx.x * 64;
    const size_t qbase = (size_t)(b * TT + q0) * CC + h * DHD;

    // load Q tile (transposed to k-major)
    for (int it = 0; it < 4; it++) {
        int idx4 = tid + it * 256;
        int r = idx4 >> 4;
        int dv = (idx4 & 15) << 2;
        float4 qv = *(const float4*)&g_q[qbase + (size_t)r * CC + dv];
        Qs[(dv + 0) * SPAD + r] = qv.x;
        Qs[(dv + 1) * SPAD + r] = qv.y;
        Qs[(dv + 2) * SPAD + r] = qv.z;
        Qs[(dv + 3) * SPAD + r] = qv.w;
    }

    float m_i[4], l_i[4], O[4][4];
#pragma unroll
    for (int i = 0; i < 4; i++) {
        m_i[i] = -INFINITY;
        l_i[i] = 0.f;
#pragma unroll
        for (int j = 0; j < 4; j++) O[i][j] = 0.f;
    }

    for (int kt = 0; kt < TT / 64; kt++) {
        __syncthreads();  // previous iteration readers done
        const size_t kbase = (size_t)(b * TT + kt * 64) * CC + h * DHD;
        // load K (k-major) and V (row-major)
        for (int it = 0; it < 4; it++) {
            int idx4 = tid + it * 256;
            int c = idx4 >> 4;
            int dv = (idx4 & 15) << 2;
            float4 kv4 = *(const float4*)&g_k[kbase + (size_t)c * CC + dv];
            KP[(dv + 0) * SPAD + c] = kv4.x;
            KP[(dv + 1) * SPAD + c] = kv4.y;
            KP[(dv + 2) * SPAD + c] = kv4.z;
            KP[(dv + 3) * SPAD + c] = kv4.w;
            float4 vv = *(const float4*)&g_v[kbase + (size_t)c * CC + dv];
            *(float4*)&Vs[c * VPAD + dv] = vv;   // VPAD=68 -> 16B aligned
        }
        if (tid < 64) {
            float xv = x[(size_t)(b * TT + kt * 64 + tid) * CC];
            kval[tid] = (xv != 0.0f) ? 0.f : -INFINITY;
        }
        __syncthreads();

        // S = Q * K^T
        float s[4][4];
#pragma unroll
        for (int i = 0; i < 4; i++)
#pragma unroll
            for (int j = 0; j < 4; j++) s[i][j] = 0.f;
#pragma unroll 8
        for (int k = 0; k < 64; k++) {
            float aq[4], bk[4];
#pragma unroll
            for (int i = 0; i < 4; i++) aq[i] = Qs[k * SPAD + ty + 16 * i];
#pragma unroll
            for (int j = 0; j < 4; j++) bk[j] = KP[k * SPAD + tx + 16 * j];
#pragma unroll
            for (int i = 0; i < 4; i++)
#pragma unroll
                for (int j = 0; j < 4; j++) s[i][j] += aq[i] * bk[j];
        }
        float km[4];
#pragma unroll
        for (int j = 0; j < 4; j++) km[j] = kval[tx + 16 * j];
        __syncthreads();  // done reading Ks before overwriting with P

#pragma unroll
        for (int i = 0; i < 4; i++)
#pragma unroll
            for (int j = 0; j < 4; j++) s[i][j] = s[i][j] * 0.125f + km[j];

        // online softmax per row
#pragma unroll
        for (int i = 0; i < 4; i++) {
            float mx = s[i][0];
#pragma unroll
            for (int j = 1; j < 4; j++) mx = fmaxf(mx, s[i][j]);
#pragma unroll
            for (int off = 8; off > 0; off >>= 1)
                mx = fmaxf(mx, __shfl_xor_sync(0xffffffffu, mx, off));
            float mnew = fmaxf(m_i[i], mx);
            float esc = __expf(m_i[i] - mnew);
            float rs = 0.f;
#pragma unroll
            for (int j = 0; j < 4; j++) {
                float p = __expf(s[i][j] - mnew);
                s[i][j] = p;
                rs += p;
            }
#pragma unroll
            for (int off = 8; off > 0; off >>= 1)
                rs += __shfl_xor_sync(0xffffffffu, rs, off);
            l_i[i] = l_i[i] * esc + rs;
            m_i[i] = mnew;
#pragma unroll
            for (int j = 0; j < 4; j++) O[i][j] *= esc;
        }

        // write P (row-major)
#pragma unroll
        for (int i = 0; i < 4; i++)
#pragma unroll
            for (int j = 0; j < 4; j++)
                KP[(ty + 16 * i) * SPAD + tx + 16 * j] = s[i][j];
        __syncthreads();

        // O += P * V
#pragma unroll 8
        for (int c = 0; c < 64; c++) {
            float pv[4], vv[4];
#pragma unroll
            for (int i = 0; i < 4; i++) pv[i] = KP[(ty + 16 * i) * SPAD + c];
#pragma unroll
            for (int j = 0; j < 4; j++) vv[j] = Vs[c * VPAD + tx + 16 * j];
#pragma unroll
            for (int i = 0; i < 4; i++)
#pragma unroll
                for (int j = 0; j < 4; j++) O[i][j] += pv[i] * vv[j];
        }
    }

    // epilogue
#pragma unroll
    for (int i = 0; i < 4; i++) {
        float inv = 1.f / l_i[i];
#pragma unroll
        for (int j = 0; j < 4; j++)
            attout[qbase + (size_t)(ty + 16 * i) * CC + tx + 16 * j] = O[i][j] * inv;
    }
}

// ---------------------------------------------------------------------------
extern "C" void kernel_launch(void* const* d_in, const int* in_sizes, int n_in,
                              void* d_out, int out_size) {
    const float* x   = (const float*)d_in[0];
    const float* wq  = (const float*)d_in[1];
    const float* bq  = (const float*)d_in[2];
    const float* wk  = (const float*)d_in[3];
    const float* bk  = (const float*)d_in[4];
    const float* wv  = (const float*)d_in[5];
    const float* bv  = (const float*)d_in[6];
    const float* wo  = (const float*)d_in[7];
    const float* bo  = (const float*)d_in[8];
    float* out = (float*)d_out;

    float *pq, *pk, *pv, *patt;
    cudaGetSymbolAddress((void**)&pq, g_q);
    cudaGetSymbolAddress((void**)&pk, g_k);
    cudaGetSymbolAddress((void**)&pv, g_v);
    cudaGetSymbolAddress((void**)&patt, g_att);

    const int attn_smem = (2 * 64 * SPAD + 64 * VPAD) * (int)sizeof(float);  // 50,688 B
    cudaFuncSetAttribute(attn_kernel, cudaFuncAttributeMaxDynamicSharedMemorySize,
                         attn_smem);

    dim3 gblk(256);
    dim3 ggrid(CC / 128, MTOT / 128);  // (8, 32)

    gemm_nt<<<ggrid, gblk>>>(x, wq, bq, pq, MTOT, CC, CC);
    gemm_nt<<<ggrid, gblk>>>(x, wk, bk, pk, MTOT, CC, CC);
    gemm_nt<<<ggrid, gblk>>>(x, wv, bv, pv, MTOT, CC, CC);

    dim3 agrid(TT / 64, BB * HH);  // (32, 32)
    attn_kernel<<<agrid, 256, attn_smem>>>(x, patt);

    gemm_nt<<<ggrid, gblk>>>(patt, wo, bo, out, MTOT, CC, CC);
}

// round 9
// speedup vs baseline: 1.4048x; 1.4048x over previous
#include <cuda_runtime.h>
#include <cuda_bf16.h>
#include <stdint.h>
#include <math.h>

#define BB 2
#define TT 2048
#define CC 1024
#define HH 16
#define DHD 64
#define MTOT (BB*TT)
#define SPAD 65
#define VPAD 68

// GEMM tensor-core tile params
#define BKG 32                 // k-chunk in elements per iteration
#define ROWBF (BKG + 8)        // bf16 elems per smem row = 40 (80 bytes) -> conflict-free ldmatrix
#define ROWB_BYTES (ROWBF * 2) // 80

// scratch (no allocation allowed)
__device__ float g_q[MTOT * CC];
__device__ float g_k[MTOT * CC];
__device__ float g_v[MTOT * CC];
__device__ float g_att[MTOT * CC];

__device__ __forceinline__ uint32_t smem_u32(const void* p) {
    return (uint32_t)__cvta_generic_to_shared(p);
}

#define LDSM_X4(r0, r1, r2, r3, addr)                                          \
    asm volatile("ldmatrix.sync.aligned.m8n8.x4.shared.b16 {%0,%1,%2,%3}, [%4];" \
                 : "=r"(r0), "=r"(r1), "=r"(r2), "=r"(r3) : "r"(addr))
#define LDSM_X2(r0, r1, addr)                                                  \
    asm volatile("ldmatrix.sync.aligned.m8n8.x2.shared.b16 {%0,%1}, [%2];"     \
                 : "=r"(r0), "=r"(r1) : "r"(addr))

#define MMA_BF16(d, a, b)                                                      \
    asm volatile("mma.sync.aligned.m16n8k16.row.col.f32.bf16.bf16.f32 "        \
                 "{%0,%1,%2,%3}, {%4,%5,%6,%7}, {%8,%9}, {%0,%1,%2,%3};"       \
                 : "+f"((d)[0]), "+f"((d)[1]), "+f"((d)[2]), "+f"((d)[3])      \
                 : "r"((a)[0]), "r"((a)[1]), "r"((a)[2]), "r"((a)[3]),         \
                   "r"((b)[0]), "r"((b)[1]))

// ---------------------------------------------------------------------------
// Tensor-core NT GEMM with bf16x3 compensation:
//   out[m,n] = sum_k A[m,k]*W[n,k] + bias[n]
//   A = Ah + Al (bf16 split); acc += Ah*Wh + Ah*Wl + Al*Wh  (~fp32 accuracy)
// 128x128 CTA tile, BK=32, 8 warps, each warp 64x32 via m16n8k16.
// ---------------------------------------------------------------------------
__global__ __launch_bounds__(256) void gemm_nt_tc(const float* __restrict__ A,
                                                  const float* __restrict__ W,
                                                  const float* __restrict__ bias,
                                                  float* __restrict__ out,
                                                  int M, int N, int K) {
    __shared__ __nv_bfloat16 Ah[128 * ROWBF];
    __shared__ __nv_bfloat16 Al[128 * ROWBF];
    __shared__ __nv_bfloat16 Wh[128 * ROWBF];
    __shared__ __nv_bfloat16 Wl[128 * ROWBF];

    const int tid = threadIdx.x;
    const int wid = tid >> 5, lane = tid & 31;
    const int warp_m = wid >> 2;      // 0..1 -> 64 rows each
    const int warp_n = wid & 3;       // 0..3 -> 32 cols each
    const int m0 = blockIdx.y * 128, n0 = blockIdx.x * 128;

    float acc[4][4][4];
#pragma unroll
    for (int mt = 0; mt < 4; mt++)
#pragma unroll
        for (int nt = 0; nt < 4; nt++)
#pragma unroll
            for (int e = 0; e < 4; e++) acc[mt][nt][e] = 0.f;

    // loader: row = tid>>1 (0..127), half = tid&1 -> k-offsets half*16 .. +15
    const int lrow = tid >> 1, lhalf = tid & 1;

    // per-thread ldmatrix byte offsets (k0-invariant part)
    uint32_t ah_base = smem_u32(Ah), al_base = smem_u32(Al);
    uint32_t wh_base = smem_u32(Wh), wl_base = smem_u32(Wl);
    uint32_t a_off[4], b_off[4];
#pragma unroll
    for (int mt = 0; mt < 4; mt++)
        a_off[mt] = (uint32_t)((warp_m * 64 + mt * 16 + (lane & 15)) * ROWB_BYTES +
                               ((lane >> 4) << 4));
#pragma unroll
    for (int nt = 0; nt < 4; nt++)
        b_off[nt] = (uint32_t)((warp_n * 32 + nt * 8 + (lane & 7)) * ROWB_BYTES +
                               (((lane >> 3) & 1) << 4));

    const int sbase = lrow * ROWBF + lhalf * 16;

    for (int k0 = 0; k0 < K; k0 += BKG) {
        // ---- load fp32 tiles, split into bf16 hi/lo, store to smem ----
        const float4* Ag = (const float4*)&A[(size_t)(m0 + lrow) * K + k0 + lhalf * 16];
        const float4* Wg = (const float4*)&W[(size_t)(n0 + lrow) * K + k0 + lhalf * 16];
#pragma unroll
        for (int j = 0; j < 4; j++) {
            float4 av = Ag[j];
            __nv_bfloat16 h0 = __float2bfloat16_rn(av.x);
            __nv_bfloat16 h1 = __float2bfloat16_rn(av.y);
            __nv_bfloat16 h2 = __float2bfloat16_rn(av.z);
            __nv_bfloat16 h3 = __float2bfloat16_rn(av.w);
            __nv_bfloat16 l0 = __float2bfloat16_rn(av.x - __bfloat162float(h0));
            __nv_bfloat16 l1 = __float2bfloat16_rn(av.y - __bfloat162float(h1));
            __nv_bfloat16 l2 = __float2bfloat16_rn(av.z - __bfloat162float(h2));
            __nv_bfloat16 l3 = __float2bfloat16_rn(av.w - __bfloat162float(h3));
            *(__nv_bfloat162*)&Ah[sbase + j * 4 + 0] = __nv_bfloat162(h0, h1);
            *(__nv_bfloat162*)&Ah[sbase + j * 4 + 2] = __nv_bfloat162(h2, h3);
            *(__nv_bfloat162*)&Al[sbase + j * 4 + 0] = __nv_bfloat162(l0, l1);
            *(__nv_bfloat162*)&Al[sbase + j * 4 + 2] = __nv_bfloat162(l2, l3);

            float4 wv = Wg[j];
            __nv_bfloat16 g0 = __float2bfloat16_rn(wv.x);
            __nv_bfloat16 g1 = __float2bfloat16_rn(wv.y);
            __nv_bfloat16 g2 = __float2bfloat16_rn(wv.z);
            __nv_bfloat16 g3 = __float2bfloat16_rn(wv.w);
            __nv_bfloat16 q0 = __float2bfloat16_rn(wv.x - __bfloat162float(g0));
            __nv_bfloat16 q1 = __float2bfloat16_rn(wv.y - __bfloat162float(g1));
            __nv_bfloat16 q2 = __float2bfloat16_rn(wv.z - __bfloat162float(g2));
            __nv_bfloat16 q3 = __float2bfloat16_rn(wv.w - __bfloat162float(g3));
            *(__nv_bfloat162*)&Wh[sbase + j * 4 + 0] = __nv_bfloat162(g0, g1);
            *(__nv_bfloat162*)&Wh[sbase + j * 4 + 2] = __nv_bfloat162(g2, g3);
            *(__nv_bfloat162*)&Wl[sbase + j * 4 + 0] = __nv_bfloat162(q0, q1);
            *(__nv_bfloat162*)&Wl[sbase + j * 4 + 2] = __nv_bfloat162(q2, q3);
        }
        __syncthreads();

        // ---- 3 compensated terms: Ah*Wh + Ah*Wl + Al*Wh ----
#pragma unroll
        for (int term = 0; term < 3; term++) {
            uint32_t abase = (term == 2) ? al_base : ah_base;
            uint32_t bbase = (term == 1) ? wl_base : wh_base;
#pragma unroll
            for (int ks = 0; ks < 2; ks++) {
                uint32_t af[4][4], bf[4][2];
#pragma unroll
                for (int mt = 0; mt < 4; mt++)
                    LDSM_X4(af[mt][0], af[mt][1], af[mt][2], af[mt][3],
                            abase + a_off[mt] + ks * 32);
#pragma unroll
                for (int nt = 0; nt < 4; nt++)
                    LDSM_X2(bf[nt][0], bf[nt][1], bbase + b_off[nt] + ks * 32);
#pragma unroll
                for (int mt = 0; mt < 4; mt++)
#pragma unroll
                    for (int nt = 0; nt < 4; nt++)
                        MMA_BF16(acc[mt][nt], af[mt], bf[nt]);
            }
        }
        __syncthreads();
    }

    // ---- epilogue: + bias, float2 stores ----
    const int g = lane >> 2, c = lane & 3;
#pragma unroll
    for (int nt = 0; nt < 4; nt++) {
        int col = n0 + warp_n * 32 + nt * 8 + c * 2;
        float b0 = bias[col], b1 = bias[col + 1];
#pragma unroll
        for (int mt = 0; mt < 4; mt++) {
            int row = m0 + warp_m * 64 + mt * 16 + g;
            float2 v0 = make_float2(acc[mt][nt][0] + b0, acc[mt][nt][1] + b1);
            float2 v1 = make_float2(acc[mt][nt][2] + b0, acc[mt][nt][3] + b1);
            *(float2*)&out[(size_t)row * N + col] = v0;
            *(float2*)&out[(size_t)(row + 8) * N + col] = v1;
        }
    }
}

// ---------------------------------------------------------------------------
// Flash attention (fp32 SIMT): one CTA per (64 q-rows, b*h)
// ---------------------------------------------------------------------------
__global__ __launch_bounds__(256) void attn_kernel(const float* __restrict__ x,
                                                   float* __restrict__ attout) {
    extern __shared__ float sm[];
    float* Qs = sm;
    float* KP = sm + 64 * SPAD;
    float* Vs = sm + 2 * 64 * SPAD;
    __shared__ float kval[64];

    const int tid = threadIdx.x;
    const int tx = tid & 15, ty = tid >> 4;
    const int bh = blockIdx.y;
    const int b = bh / HH, h = bh % HH;
    const int q0 = blockIdx.x * 64;
    const size_t qbase = (size_t)(b * TT + q0) * CC + h * DHD;

    for (int it = 0; it < 4; it++) {
        int idx4 = tid + it * 256;
        int r = idx4 >> 4;
        int dv = (idx4 & 15) << 2;
        float4 qv = *(const float4*)&g_q[qbase + (size_t)r * CC + dv];
        Qs[(dv + 0) * SPAD + r] = qv.x;
        Qs[(dv + 1) * SPAD + r] = qv.y;
        Qs[(dv + 2) * SPAD + r] = qv.z;
        Qs[(dv + 3) * SPAD + r] = qv.w;
    }

    float m_i[4], l_i[4], O[4][4];
#pragma unroll
    for (int i = 0; i < 4; i++) {
        m_i[i] = -INFINITY;
        l_i[i] = 0.f;
#pragma unroll
        for (int j = 0; j < 4; j++) O[i][j] = 0.f;
    }

    for (int kt = 0; kt < TT / 64; kt++) {
        __syncthreads();
        const size_t kbase = (size_t)(b * TT + kt * 64) * CC + h * DHD;
        for (int it = 0; it < 4; it++) {
            int idx4 = tid + it * 256;
            int c = idx4 >> 4;
            int dv = (idx4 & 15) << 2;
            float4 kv4 = *(const float4*)&g_k[kbase + (size_t)c * CC + dv];
            KP[(dv + 0) * SPAD + c] = kv4.x;
            KP[(dv + 1) * SPAD + c] = kv4.y;
            KP[(dv + 2) * SPAD + c] = kv4.z;
            KP[(dv + 3) * SPAD + c] = kv4.w;
            float4 vv = *(const float4*)&g_v[kbase + (size_t)c * CC + dv];
            *(float4*)&Vs[c * VPAD + dv] = vv;
        }
        if (tid < 64) {
            float xv = x[(size_t)(b * TT + kt * 64 + tid) * CC];
            kval[tid] = (xv != 0.0f) ? 0.f : -INFINITY;
        }
        __syncthreads();

        float s[4][4];
#pragma unroll
        for (int i = 0; i < 4; i++)
#pragma unroll
            for (int j = 0; j < 4; j++) s[i][j] = 0.f;
#pragma unroll 8
        for (int k = 0; k < 64; k++) {
            float aq[4], bk[4];
#pragma unroll
            for (int i = 0; i < 4; i++) aq[i] = Qs[k * SPAD + ty + 16 * i];
#pragma unroll
            for (int j = 0; j < 4; j++) bk[j] = KP[k * SPAD + tx + 16 * j];
#pragma unroll
            for (int i = 0; i < 4; i++)
#pragma unroll
                for (int j = 0; j < 4; j++) s[i][j] += aq[i] * bk[j];
        }
        float km[4];
#pragma unroll
        for (int j = 0; j < 4; j++) km[j] = kval[tx + 16 * j];
        __syncthreads();

#pragma unroll
        for (int i = 0; i < 4; i++)
#pragma unroll
            for (int j = 0; j < 4; j++) s[i][j] = s[i][j] * 0.125f + km[j];

#pragma unroll
        for (int i = 0; i < 4; i++) {
            float mx = s[i][0];
#pragma unroll
            for (int j = 1; j < 4; j++) mx = fmaxf(mx, s[i][j]);
#pragma unroll
            for (int off = 8; off > 0; off >>= 1)
                mx = fmaxf(mx, __shfl_xor_sync(0xffffffffu, mx, off));
            float mnew = fmaxf(m_i[i], mx);
            float esc = __expf(m_i[i] - mnew);
            float rs = 0.f;
#pragma unroll
            for (int j = 0; j < 4; j++) {
                float p = __expf(s[i][j] - mnew);
                s[i][j] = p;
                rs += p;
            }
#pragma unroll
            for (int off = 8; off > 0; off >>= 1)
                rs += __shfl_xor_sync(0xffffffffu, rs, off);
            l_i[i] = l_i[i] * esc + rs;
            m_i[i] = mnew;
#pragma unroll
            for (int j = 0; j < 4; j++) O[i][j] *= esc;
        }

#pragma unroll
        for (int i = 0; i < 4; i++)
#pragma unroll
            for (int j = 0; j < 4; j++)
                KP[(ty + 16 * i) * SPAD + tx + 16 * j] = s[i][j];
        __syncthreads();

#pragma unroll 8
        for (int c = 0; c < 64; c++) {
            float pv[4], vv[4];
#pragma unroll
            for (int i = 0; i < 4; i++) pv[i] = KP[(ty + 16 * i) * SPAD + c];
#pragma unroll
            for (int j = 0; j < 4; j++) vv[j] = Vs[c * VPAD + tx + 16 * j];
#pragma unroll
            for (int i = 0; i < 4; i++)
#pragma unroll
                for (int j = 0; j < 4; j++) O[i][j] += pv[i] * vv[j];
        }
    }

#pragma unroll
    for (int i = 0; i < 4; i++) {
        float inv = 1.f / l_i[i];
#pragma unroll
        for (int j = 0; j < 4; j++)
            attout[qbase + (size_t)(ty + 16 * i) * CC + tx + 16 * j] = O[i][j] * inv;
    }
}

// ---------------------------------------------------------------------------
extern "C" void kernel_launch(void* const* d_in, const int* in_sizes, int n_in,
                              void* d_out, int out_size) {
    const float* x   = (const float*)d_in[0];
    const float* wq  = (const float*)d_in[1];
    const float* bq  = (const float*)d_in[2];
    const float* wk  = (const float*)d_in[3];
    const float* bk  = (const float*)d_in[4];
    const float* wv  = (const float*)d_in[5];
    const float* bv  = (const float*)d_in[6];
    const float* wo  = (const float*)d_in[7];
    const float* bo  = (const float*)d_in[8];
    float* out = (float*)d_out;

    float *pq, *pk, *pv, *patt;
    cudaGetSymbolAddress((void**)&pq, g_q);
    cudaGetSymbolAddress((void**)&pk, g_k);
    cudaGetSymbolAddress((void**)&pv, g_v);
    cudaGetSymbolAddress((void**)&patt, g_att);

    const int attn_smem = (2 * 64 * SPAD + 64 * VPAD) * (int)sizeof(float);
    cudaFuncSetAttribute(attn_kernel, cudaFuncAttributeMaxDynamicSharedMemorySize,
                         attn_smem);

    dim3 gblk(256);
    dim3 ggrid(CC / 128, MTOT / 128);  // (8, 32)

    gemm_nt_tc<<<ggrid, gblk>>>(x, wq, bq, pq, MTOT, CC, CC);
    gemm_nt_tc<<<ggrid, gblk>>>(x, wk, bk, pk, MTOT, CC, CC);
    gemm_nt_tc<<<ggrid, gblk>>>(x, wv, bv, pv, MTOT, CC, CC);

    dim3 agrid(TT / 64, BB * HH);  // (32, 32)
    attn_kernel<<<agrid, 256, attn_smem>>>(x, patt);

    gemm_nt_tc<<<ggrid, gblk>>>(patt, wo, bo, out, MTOT, CC, CC);
}

// round 10
// speedup vs baseline: 2.4648x; 1.7545x over previous
#include <cuda_runtime.h>
#include <cuda_bf16.h>
#include <stdint.h>
#include <math.h>

#define BB 2
#define TT 2048
#define CC 1024
#define HH 16
#define DHD 64
#define MTOT (BB*TT)

// GEMM tensor-core tile params
#define BKG 32
#define ROWBF (BKG + 8)        // 40 bf16 = 80 B row
#define ROWB_BYTES (ROWBF * 2)

// Attention smem row: 64 dh/key + 8 pad = 72 bf16 = 144 B (9x16B -> conflict-free)
#define ROWA 72
#define ROWA_B (ROWA * 2)

// scratch (no allocation allowed)
__device__ float g_q[MTOT * CC];
__device__ float g_k[MTOT * CC];
__device__ float g_v[MTOT * CC];
__device__ float g_att[MTOT * CC];

__device__ __forceinline__ uint32_t smem_u32(const void* p) {
    return (uint32_t)__cvta_generic_to_shared(p);
}

#define LDSM_X4(r0, r1, r2, r3, addr)                                          \
    asm volatile("ldmatrix.sync.aligned.m8n8.x4.shared.b16 {%0,%1,%2,%3}, [%4];" \
                 : "=r"(r0), "=r"(r1), "=r"(r2), "=r"(r3) : "r"(addr))
#define LDSM_X2(r0, r1, addr)                                                  \
    asm volatile("ldmatrix.sync.aligned.m8n8.x2.shared.b16 {%0,%1}, [%2];"     \
                 : "=r"(r0), "=r"(r1) : "r"(addr))
#define LDSM_X2_T(r0, r1, addr)                                                \
    asm volatile("ldmatrix.sync.aligned.m8n8.x2.trans.shared.b16 {%0,%1}, [%2];" \
                 : "=r"(r0), "=r"(r1) : "r"(addr))

#define MMA_BF16(d, a, b)                                                      \
    asm volatile("mma.sync.aligned.m16n8k16.row.col.f32.bf16.bf16.f32 "        \
                 "{%0,%1,%2,%3}, {%4,%5,%6,%7}, {%8,%9}, {%0,%1,%2,%3};"       \
                 : "+f"((d)[0]), "+f"((d)[1]), "+f"((d)[2]), "+f"((d)[3])      \
                 : "r"((a)[0]), "r"((a)[1]), "r"((a)[2]), "r"((a)[3]),         \
                   "r"((b)[0]), "r"((b)[1]))

// split fp32 pair -> packed bf16 hi + packed bf16 residual
__device__ __forceinline__ void split2(float a, float b, uint32_t& hi, uint32_t& lo) {
    __nv_bfloat162 h = __float22bfloat162_rn(make_float2(a, b));
    float2 hf = __bfloat1622float2(h);
    __nv_bfloat162 l = __float22bfloat162_rn(make_float2(a - hf.x, b - hf.y));
    hi = *reinterpret_cast<uint32_t*>(&h);
    lo = *reinterpret_cast<uint32_t*>(&l);
}

// ---------------------------------------------------------------------------
// Tensor-core NT GEMM with bf16x3 compensation (unchanged from R9, passing)
// ---------------------------------------------------------------------------
__global__ __launch_bounds__(256) void gemm_nt_tc(const float* __restrict__ A,
                                                  const float* __restrict__ W,
                                                  const float* __restrict__ bias,
                                                  float* __restrict__ out,
                                                  int M, int N, int K) {
    __shared__ __nv_bfloat16 Ah[128 * ROWBF];
    __shared__ __nv_bfloat16 Al[128 * ROWBF];
    __shared__ __nv_bfloat16 Wh[128 * ROWBF];
    __shared__ __nv_bfloat16 Wl[128 * ROWBF];

    const int tid = threadIdx.x;
    const int wid = tid >> 5, lane = tid & 31;
    const int warp_m = wid >> 2;
    const int warp_n = wid & 3;
    const int m0 = blockIdx.y * 128, n0 = blockIdx.x * 128;

    float acc[4][4][4];
#pragma unroll
    for (int mt = 0; mt < 4; mt++)
#pragma unroll
        for (int nt = 0; nt < 4; nt++)
#pragma unroll
            for (int e = 0; e < 4; e++) acc[mt][nt][e] = 0.f;

    const int lrow = tid >> 1, lhalf = tid & 1;

    uint32_t ah_base = smem_u32(Ah), al_base = smem_u32(Al);
    uint32_t wh_base = smem_u32(Wh), wl_base = smem_u32(Wl);
    uint32_t a_off[4], b_off[4];
#pragma unroll
    for (int mt = 0; mt < 4; mt++)
        a_off[mt] = (uint32_t)((warp_m * 64 + mt * 16 + (lane & 15)) * ROWB_BYTES +
                               ((lane >> 4) << 4));
#pragma unroll
    for (int nt = 0; nt < 4; nt++)
        b_off[nt] = (uint32_t)((warp_n * 32 + nt * 8 + (lane & 7)) * ROWB_BYTES +
                               (((lane >> 3) & 1) << 4));

    const int sbase = lrow * ROWBF + lhalf * 16;

    for (int k0 = 0; k0 < K; k0 += BKG) {
        const float4* Ag = (const float4*)&A[(size_t)(m0 + lrow) * K + k0 + lhalf * 16];
        const float4* Wg = (const float4*)&W[(size_t)(n0 + lrow) * K + k0 + lhalf * 16];
#pragma unroll
        for (int j = 0; j < 4; j++) {
            float4 av = Ag[j];
            uint32_t h01, l01, h23, l23;
            split2(av.x, av.y, h01, l01);
            split2(av.z, av.w, h23, l23);
            *(uint32_t*)&Ah[sbase + j * 4 + 0] = h01;
            *(uint32_t*)&Ah[sbase + j * 4 + 2] = h23;
            *(uint32_t*)&Al[sbase + j * 4 + 0] = l01;
            *(uint32_t*)&Al[sbase + j * 4 + 2] = l23;

            float4 wv = Wg[j];
            split2(wv.x, wv.y, h01, l01);
            split2(wv.z, wv.w, h23, l23);
            *(uint32_t*)&Wh[sbase + j * 4 + 0] = h01;
            *(uint32_t*)&Wh[sbase + j * 4 + 2] = h23;
            *(uint32_t*)&Wl[sbase + j * 4 + 0] = l01;
            *(uint32_t*)&Wl[sbase + j * 4 + 2] = l23;
        }
        __syncthreads();

#pragma unroll
        for (int term = 0; term < 3; term++) {
            uint32_t abase = (term == 2) ? al_base : ah_base;
            uint32_t bbase = (term == 1) ? wl_base : wh_base;
#pragma unroll
            for (int ks = 0; ks < 2; ks++) {
                uint32_t af[4][4], bf[4][2];
#pragma unroll
                for (int mt = 0; mt < 4; mt++)
                    LDSM_X4(af[mt][0], af[mt][1], af[mt][2], af[mt][3],
                            abase + a_off[mt] + ks * 32);
#pragma unroll
                for (int nt = 0; nt < 4; nt++)
                    LDSM_X2(bf[nt][0], bf[nt][1], bbase + b_off[nt] + ks * 32);
#pragma unroll
                for (int mt = 0; mt < 4; mt++)
#pragma unroll
                    for (int nt = 0; nt < 4; nt++)
                        MMA_BF16(acc[mt][nt], af[mt], bf[nt]);
            }
        }
        __syncthreads();
    }

    const int g = lane >> 2, c = lane & 3;
#pragma unroll
    for (int nt = 0; nt < 4; nt++) {
        int col = n0 + warp_n * 32 + nt * 8 + c * 2;
        float b0 = bias[col], b1 = bias[col + 1];
#pragma unroll
        for (int mt = 0; mt < 4; mt++) {
            int row = m0 + warp_m * 64 + mt * 16 + g;
            float2 v0 = make_float2(acc[mt][nt][0] + b0, acc[mt][nt][1] + b1);
            float2 v1 = make_float2(acc[mt][nt][2] + b0, acc[mt][nt][3] + b1);
            *(float2*)&out[(size_t)row * N + col] = v0;
            *(float2*)&out[(size_t)(row + 8) * N + col] = v1;
        }
    }
}

// ---------------------------------------------------------------------------
// Tensor-core flash attention, bf16x3 compensated.
// CTA: 128 q-rows x one (b,h). 8 warps, each warp: 16 q-rows x 64 keys x 64 dh.
// Smem (bf16, dynamic): Qh[128][72] Ql | Kh[64][72] Kl | Vh[64][72] Vl
// ---------------------------------------------------------------------------
__global__ __launch_bounds__(256) void attn_tc(const float* __restrict__ x,
                                               float* __restrict__ attout) {
    extern __shared__ __nv_bfloat16 smb[];
    __nv_bfloat16* Qh = smb;                 // 128*72
    __nv_bfloat16* Ql = Qh + 128 * ROWA;
    __nv_bfloat16* Kh = Ql + 128 * ROWA;     // 64*72
    __nv_bfloat16* Kl = Kh + 64 * ROWA;
    __nv_bfloat16* Vh = Kl + 64 * ROWA;
    __nv_bfloat16* Vl = Vh + 64 * ROWA;
    __shared__ float kval[64];

    const int tid = threadIdx.x;
    const int w = tid >> 5, lane = tid & 31;
    const int g = lane >> 2, qc = lane & 3;
    const int bh = blockIdx.y;
    const int b = bh / HH, h = bh % HH;
    const int q0 = blockIdx.x * 128;

    const uint32_t qh_base = smem_u32(Qh), ql_base = smem_u32(Ql);
    const uint32_t kh_base = smem_u32(Kh), kl_base = smem_u32(Kl);
    const uint32_t vh_base = smem_u32(Vh), vl_base = smem_u32(Vl);

    // ---- load + split Q tile (128 x 64), row-major padded ----
    {
        const int row = tid >> 1, half = tid & 1;
        const float4* Qg = (const float4*)&g_q[(size_t)(b * TT + q0 + row) * CC +
                                               h * DHD + half * 32];
        const int sb = row * ROWA + half * 32;
#pragma unroll
        for (int j = 0; j < 8; j++) {
            float4 v = Qg[j];
            uint32_t h01, l01, h23, l23;
            split2(v.x, v.y, h01, l01);
            split2(v.z, v.w, h23, l23);
            *(uint32_t*)&Qh[sb + j * 4 + 0] = h01;
            *(uint32_t*)&Qh[sb + j * 4 + 2] = h23;
            *(uint32_t*)&Ql[sb + j * 4 + 0] = l01;
            *(uint32_t*)&Ql[sb + j * 4 + 2] = l23;
        }
    }
    __syncthreads();

    // ---- Q fragments in registers, reused for all key tiles ----
    uint32_t qf_h[4][4], qf_l[4][4];
    {
        uint32_t aoff = (uint32_t)((w * 16 + (lane & 15)) * ROWA_B + ((lane >> 4) << 4));
#pragma unroll
        for (int ks = 0; ks < 4; ks++) {
            LDSM_X4(qf_h[ks][0], qf_h[ks][1], qf_h[ks][2], qf_h[ks][3],
                    qh_base + aoff + ks * 32);
            LDSM_X4(qf_l[ks][0], qf_l[ks][1], qf_l[ks][2], qf_l[ks][3],
                    ql_base + aoff + ks * 32);
        }
    }

    float oacc[8][4];
#pragma unroll
    for (int jd = 0; jd < 8; jd++)
#pragma unroll
        for (int e = 0; e < 4; e++) oacc[jd][e] = 0.f;
    float m0i = -INFINITY, m1i = -INFINITY, l0i = 0.f, l1i = 0.f;

    for (int kt = 0; kt < TT / 64; kt++) {
        __syncthreads();  // prior readers of K/V smem done
        // ---- load + split K, V tiles (64 x 64) ----
        {
            const int row = tid >> 2, qq = tid & 3;
            const size_t gb = (size_t)(b * TT + kt * 64 + row) * CC + h * DHD + qq * 16;
            const float4* Kg = (const float4*)&g_k[gb];
            const float4* Vg = (const float4*)&g_v[gb];
            const int sb = row * ROWA + qq * 16;
#pragma unroll
            for (int j = 0; j < 4; j++) {
                float4 v = Kg[j];
                uint32_t h01, l01, h23, l23;
                split2(v.x, v.y, h01, l01);
                split2(v.z, v.w, h23, l23);
                *(uint32_t*)&Kh[sb + j * 4 + 0] = h01;
                *(uint32_t*)&Kh[sb + j * 4 + 2] = h23;
                *(uint32_t*)&Kl[sb + j * 4 + 0] = l01;
                *(uint32_t*)&Kl[sb + j * 4 + 2] = l23;
                v = Vg[j];
                split2(v.x, v.y, h01, l01);
                split2(v.z, v.w, h23, l23);
                *(uint32_t*)&Vh[sb + j * 4 + 0] = h01;
                *(uint32_t*)&Vh[sb + j * 4 + 2] = h23;
                *(uint32_t*)&Vl[sb + j * 4 + 0] = l01;
                *(uint32_t*)&Vl[sb + j * 4 + 2] = l23;
            }
        }
        if (tid < 64) {
            float xv = x[(size_t)(b * TT + kt * 64 + tid) * CC];
            kval[tid] = (xv != 0.0f) ? 0.f : -INFINITY;
        }
        __syncthreads();

        // ---- S = Q K^T (3-term compensated), per warp 16x64 ----
        float sacc[8][4];
#pragma unroll
        for (int j = 0; j < 8; j++)
#pragma unroll
            for (int e = 0; e < 4; e++) sacc[j][e] = 0.f;

#pragma unroll
        for (int ks = 0; ks < 4; ks++) {
#pragma unroll
            for (int j = 0; j < 8; j++) {
                uint32_t boff = (uint32_t)((j * 8 + (lane & 7)) * ROWA_B +
                                           (((lane >> 3) & 1) << 4) + ks * 32);
                uint32_t bh2[2], bl2[2];
                LDSM_X2(bh2[0], bh2[1], kh_base + boff);
                LDSM_X2(bl2[0], bl2[1], kl_base + boff);
                MMA_BF16(sacc[j], qf_h[ks], bh2);
                MMA_BF16(sacc[j], qf_h[ks], bl2);
                MMA_BF16(sacc[j], qf_l[ks], bh2);
            }
        }

        // ---- scale + mask ----
#pragma unroll
        for (int j = 0; j < 8; j++) {
            float km0 = kval[j * 8 + 2 * qc];
            float km1 = kval[j * 8 + 2 * qc + 1];
            sacc[j][0] = sacc[j][0] * 0.125f + km0;
            sacc[j][1] = sacc[j][1] * 0.125f + km1;
            sacc[j][2] = sacc[j][2] * 0.125f + km0;
            sacc[j][3] = sacc[j][3] * 0.125f + km1;
        }

        // ---- online softmax (rows g, g+8; 4 lanes per row group) ----
        float mx0 = -INFINITY, mx1 = -INFINITY;
#pragma unroll
        for (int j = 0; j < 8; j++) {
            mx0 = fmaxf(mx0, fmaxf(sacc[j][0], sacc[j][1]));
            mx1 = fmaxf(mx1, fmaxf(sacc[j][2], sacc[j][3]));
        }
        mx0 = fmaxf(mx0, __shfl_xor_sync(0xffffffffu, mx0, 1));
        mx0 = fmaxf(mx0, __shfl_xor_sync(0xffffffffu, mx0, 2));
        mx1 = fmaxf(mx1, __shfl_xor_sync(0xffffffffu, mx1, 1));
        mx1 = fmaxf(mx1, __shfl_xor_sync(0xffffffffu, mx1, 2));
        float mn0 = fmaxf(m0i, mx0), mn1 = fmaxf(m1i, mx1);
        float esc0 = __expf(m0i - mn0), esc1 = __expf(m1i - mn1);
        float rs0 = 0.f, rs1 = 0.f;
#pragma unroll
        for (int j = 0; j < 8; j++) {
            float p0 = __expf(sacc[j][0] - mn0);
            float p1 = __expf(sacc[j][1] - mn0);
            float p2 = __expf(sacc[j][2] - mn1);
            float p3 = __expf(sacc[j][3] - mn1);
            sacc[j][0] = p0; sacc[j][1] = p1; sacc[j][2] = p2; sacc[j][3] = p3;
            rs0 += p0 + p1;
            rs1 += p2 + p3;
        }
        rs0 += __shfl_xor_sync(0xffffffffu, rs0, 1);
        rs0 += __shfl_xor_sync(0xffffffffu, rs0, 2);
        rs1 += __shfl_xor_sync(0xffffffffu, rs1, 1);
        rs1 += __shfl_xor_sync(0xffffffffu, rs1, 2);
        l0i = l0i * esc0 + rs0;
        l1i = l1i * esc1 + rs1;
        m0i = mn0; m1i = mn1;
#pragma unroll
        for (int jd = 0; jd < 8; jd++) {
            oacc[jd][0] *= esc0; oacc[jd][1] *= esc0;
            oacc[jd][2] *= esc1; oacc[jd][3] *= esc1;
        }

        // ---- P -> bf16 hi/lo A fragments (register-only conversion) ----
        uint32_t pf_h[4][4], pf_l[4][4];
#pragma unroll
        for (int ks = 0; ks < 4; ks++) {
            int j0 = 2 * ks, j1 = 2 * ks + 1;
            split2(sacc[j0][0], sacc[j0][1], pf_h[ks][0], pf_l[ks][0]);
            split2(sacc[j0][2], sacc[j0][3], pf_h[ks][1], pf_l[ks][1]);
            split2(sacc[j1][0], sacc[j1][1], pf_h[ks][2], pf_l[ks][2]);
            split2(sacc[j1][2], sacc[j1][3], pf_h[ks][3], pf_l[ks][3]);
        }

        // ---- O += P V (3-term compensated); V via ldmatrix.trans ----
#pragma unroll
        for (int jd = 0; jd < 8; jd++) {
#pragma unroll
            for (int ks = 0; ks < 4; ks++) {
                uint32_t boff = (uint32_t)((ks * 16 + (lane & 15)) * ROWA_B + jd * 16);
                uint32_t bvh[2], bvl[2];
                LDSM_X2_T(bvh[0], bvh[1], vh_base + boff);
                LDSM_X2_T(bvl[0], bvl[1], vl_base + boff);
                MMA_BF16(oacc[jd], pf_h[ks], bvh);
                MMA_BF16(oacc[jd], pf_h[ks], bvl);
                MMA_BF16(oacc[jd], pf_l[ks], bvh);
            }
        }
    }

    // ---- epilogue: normalize + store ----
    float inv0 = 1.f / l0i, inv1 = 1.f / l1i;
    const int r0 = q0 + w * 16 + g;
    const size_t obase = (size_t)(b * TT + r0) * CC + h * DHD;
#pragma unroll
    for (int jd = 0; jd < 8; jd++) {
        int col = jd * 8 + 2 * qc;
        *(float2*)&attout[obase + col] =
            make_float2(oacc[jd][0] * inv0, oacc[jd][1] * inv0);
        *(float2*)&attout[obase + 8 * CC + col] =
            make_float2(oacc[jd][2] * inv1, oacc[jd][3] * inv1);
    }
}

// ---------------------------------------------------------------------------
extern "C" void kernel_launch(void* const* d_in, const int* in_sizes, int n_in,
                              void* d_out, int out_size) {
    const float* x   = (const float*)d_in[0];
    const float* wq  = (const float*)d_in[1];
    const float* bq  = (const float*)d_in[2];
    const float* wk  = (const float*)d_in[3];
    const float* bk  = (const float*)d_in[4];
    const float* wv  = (const float*)d_in[5];
    const float* bv  = (const float*)d_in[6];
    const float* wo  = (const float*)d_in[7];
    const float* bo  = (const float*)d_in[8];
    float* out = (float*)d_out;

    float *pq, *pk, *pv, *patt;
    cudaGetSymbolAddress((void**)&pq, g_q);
    cudaGetSymbolAddress((void**)&pk, g_k);
    cudaGetSymbolAddress((void**)&pv, g_v);
    cudaGetSymbolAddress((void**)&patt, g_att);

    const int attn_smem = (128 + 64 + 64) * ROWA * 2 * 2;  // 73,728 B
    cudaFuncSetAttribute(attn_tc, cudaFuncAttributeMaxDynamicSharedMemorySize,
                         attn_smem);

    dim3 gblk(256);
    dim3 ggrid(CC / 128, MTOT / 128);  // (8, 32)

    gemm_nt_tc<<<ggrid, gblk>>>(x, wq, bq, pq, MTOT, CC, CC);
    gemm_nt_tc<<<ggrid, gblk>>>(x, wk, bk, pk, MTOT, CC, CC);
    gemm_nt_tc<<<ggrid, gblk>>>(x, wv, bv, pv, MTOT, CC, CC);

    dim3 agrid(TT / 128, BB * HH);  // (16, 32)
    attn_tc<<<agrid, 256, attn_smem>>>(x, patt);

    gemm_nt_tc<<<ggrid, gblk>>>(patt, wo, bo, out, MTOT, CC, CC);
}

// round 11
// speedup vs baseline: 2.6923x; 1.0923x over previous
#include <cuda_runtime.h>
#include <cuda_bf16.h>
#include <stdint.h>
#include <math.h>

#define BB 2
#define TT 2048
#define CC 1024
#define HH 16
#define DHD 64
#define MTOT (BB*TT)

// GEMM tensor-core tile params
#define BKG 32
#define ROWBF (BKG + 8)        // 40 bf16 = 80 B row
#define ROWB_BYTES (ROWBF * 2)

// Attention smem row: 64 dh/key + 8 pad = 72 bf16 = 144 B (9x16B -> conflict-free)
#define ROWA 72
#define ROWA_B (ROWA * 2)

// scratch (no allocation allowed)
__device__ float g_q[MTOT * CC];
__device__ float g_k[MTOT * CC];
__device__ float g_v[MTOT * CC];
__device__ float g_att[MTOT * CC];

__device__ __forceinline__ uint32_t smem_u32(const void* p) {
    return (uint32_t)__cvta_generic_to_shared(p);
}

#define LDSM_X4(r0, r1, r2, r3, addr)                                          \
    asm volatile("ldmatrix.sync.aligned.m8n8.x4.shared.b16 {%0,%1,%2,%3}, [%4];" \
                 : "=r"(r0), "=r"(r1), "=r"(r2), "=r"(r3) : "r"(addr))
#define LDSM_X2(r0, r1, addr)                                                  \
    asm volatile("ldmatrix.sync.aligned.m8n8.x2.shared.b16 {%0,%1}, [%2];"     \
                 : "=r"(r0), "=r"(r1) : "r"(addr))
#define LDSM_X2_T(r0, r1, addr)                                                \
    asm volatile("ldmatrix.sync.aligned.m8n8.x2.trans.shared.b16 {%0,%1}, [%2];" \
                 : "=r"(r0), "=r"(r1) : "r"(addr))

#define MMA_BF16(d, a, b)                                                      \
    asm volatile("mma.sync.aligned.m16n8k16.row.col.f32.bf16.bf16.f32 "        \
                 "{%0,%1,%2,%3}, {%4,%5,%6,%7}, {%8,%9}, {%0,%1,%2,%3};"       \
                 : "+f"((d)[0]), "+f"((d)[1]), "+f"((d)[2]), "+f"((d)[3])      \
                 : "r"((a)[0]), "r"((a)[1]), "r"((a)[2]), "r"((a)[3]),         \
                   "r"((b)[0]), "r"((b)[1]))

// split fp32 pair -> packed bf16 hi + packed bf16 residual
__device__ __forceinline__ void split2(float a, float b, uint32_t& hi, uint32_t& lo) {
    __nv_bfloat162 h = __float22bfloat162_rn(make_float2(a, b));
    float2 hf = __bfloat1622float2(h);
    __nv_bfloat162 l = __float22bfloat162_rn(make_float2(a - hf.x, b - hf.y));
    hi = *reinterpret_cast<uint32_t*>(&h);
    lo = *reinterpret_cast<uint32_t*>(&l);
}

// ---------------------------------------------------------------------------
// Tensor-core NT GEMM with bf16x3 compensation (unchanged; passing @ ~105us)
// ---------------------------------------------------------------------------
__global__ __launch_bounds__(256) void gemm_nt_tc(const float* __restrict__ A,
                                                  const float* __restrict__ W,
                                                  const float* __restrict__ bias,
                                                  float* __restrict__ out,
                                                  int M, int N, int K) {
    __shared__ __nv_bfloat16 Ah[128 * ROWBF];
    __shared__ __nv_bfloat16 Al[128 * ROWBF];
    __shared__ __nv_bfloat16 Wh[128 * ROWBF];
    __shared__ __nv_bfloat16 Wl[128 * ROWBF];

    const int tid = threadIdx.x;
    const int wid = tid >> 5, lane = tid & 31;
    const int warp_m = wid >> 2;
    const int warp_n = wid & 3;
    const int m0 = blockIdx.y * 128, n0 = blockIdx.x * 128;

    float acc[4][4][4];
#pragma unroll
    for (int mt = 0; mt < 4; mt++)
#pragma unroll
        for (int nt = 0; nt < 4; nt++)
#pragma unroll
            for (int e = 0; e < 4; e++) acc[mt][nt][e] = 0.f;

    const int lrow = tid >> 1, lhalf = tid & 1;

    uint32_t ah_base = smem_u32(Ah), al_base = smem_u32(Al);
    uint32_t wh_base = smem_u32(Wh), wl_base = smem_u32(Wl);
    uint32_t a_off[4], b_off[4];
#pragma unroll
    for (int mt = 0; mt < 4; mt++)
        a_off[mt] = (uint32_t)((warp_m * 64 + mt * 16 + (lane & 15)) * ROWB_BYTES +
                               ((lane >> 4) << 4));
#pragma unroll
    for (int nt = 0; nt < 4; nt++)
        b_off[nt] = (uint32_t)((warp_n * 32 + nt * 8 + (lane & 7)) * ROWB_BYTES +
                               (((lane >> 3) & 1) << 4));

    const int sbase = lrow * ROWBF + lhalf * 16;

    for (int k0 = 0; k0 < K; k0 += BKG) {
        const float4* Ag = (const float4*)&A[(size_t)(m0 + lrow) * K + k0 + lhalf * 16];
        const float4* Wg = (const float4*)&W[(size_t)(n0 + lrow) * K + k0 + lhalf * 16];
#pragma unroll
        for (int j = 0; j < 4; j++) {
            float4 av = Ag[j];
            uint32_t h01, l01, h23, l23;
            split2(av.x, av.y, h01, l01);
            split2(av.z, av.w, h23, l23);
            *(uint32_t*)&Ah[sbase + j * 4 + 0] = h01;
            *(uint32_t*)&Ah[sbase + j * 4 + 2] = h23;
            *(uint32_t*)&Al[sbase + j * 4 + 0] = l01;
            *(uint32_t*)&Al[sbase + j * 4 + 2] = l23;

            float4 wv = Wg[j];
            split2(wv.x, wv.y, h01, l01);
            split2(wv.z, wv.w, h23, l23);
            *(uint32_t*)&Wh[sbase + j * 4 + 0] = h01;
            *(uint32_t*)&Wh[sbase + j * 4 + 2] = h23;
            *(uint32_t*)&Wl[sbase + j * 4 + 0] = l01;
            *(uint32_t*)&Wl[sbase + j * 4 + 2] = l23;
        }
        __syncthreads();

#pragma unroll
        for (int term = 0; term < 3; term++) {
            uint32_t abase = (term == 2) ? al_base : ah_base;
            uint32_t bbase = (term == 1) ? wl_base : wh_base;
#pragma unroll
            for (int ks = 0; ks < 2; ks++) {
                uint32_t af[4][4], bf[4][2];
#pragma unroll
                for (int mt = 0; mt < 4; mt++)
                    LDSM_X4(af[mt][0], af[mt][1], af[mt][2], af[mt][3],
                            abase + a_off[mt] + ks * 32);
#pragma unroll
                for (int nt = 0; nt < 4; nt++)
                    LDSM_X2(bf[nt][0], bf[nt][1], bbase + b_off[nt] + ks * 32);
#pragma unroll
                for (int mt = 0; mt < 4; mt++)
#pragma unroll
                    for (int nt = 0; nt < 4; nt++)
                        MMA_BF16(acc[mt][nt], af[mt], bf[nt]);
            }
        }
        __syncthreads();
    }

    const int g = lane >> 2, c = lane & 3;
#pragma unroll
    for (int nt = 0; nt < 4; nt++) {
        int col = n0 + warp_n * 32 + nt * 8 + c * 2;
        float b0 = bias[col], b1 = bias[col + 1];
#pragma unroll
        for (int mt = 0; mt < 4; mt++) {
            int row = m0 + warp_m * 64 + mt * 16 + g;
            float2 v0 = make_float2(acc[mt][nt][0] + b0, acc[mt][nt][1] + b1);
            float2 v1 = make_float2(acc[mt][nt][2] + b0, acc[mt][nt][3] + b1);
            *(float2*)&out[(size_t)row * N + col] = v0;
            *(float2*)&out[(size_t)(row + 8) * N + col] = v1;
        }
    }
}

// ---------------------------------------------------------------------------
// Tensor-core flash attention, bf16x3 compensated.
// CTA: 128 q-rows x one (b,h). 8 warps, each warp: 16 q-rows x 64 keys x 64 dh.
// __launch_bounds__(256, 2): cap regs at 128 -> 2 CTAs/SM (occupancy fix).
// Q-lo fragments are re-loaded from smem per key tile to cut register pressure.
// ---------------------------------------------------------------------------
__global__ __launch_bounds__(256, 2) void attn_tc(const float* __restrict__ x,
                                                  float* __restrict__ attout) {
    extern __shared__ __nv_bfloat16 smb[];
    __nv_bfloat16* Qh = smb;                 // 128*72
    __nv_bfloat16* Ql = Qh + 128 * ROWA;
    __nv_bfloat16* Kh = Ql + 128 * ROWA;     // 64*72
    __nv_bfloat16* Kl = Kh + 64 * ROWA;
    __nv_bfloat16* Vh = Kl + 64 * ROWA;
    __nv_bfloat16* Vl = Vh + 64 * ROWA;
    __shared__ float kval[64];

    const int tid = threadIdx.x;
    const int w = tid >> 5, lane = tid & 31;
    const int g = lane >> 2, qc = lane & 3;
    const int bh = blockIdx.y;
    const int b = bh / HH, h = bh % HH;
    const int q0 = blockIdx.x * 128;

    const uint32_t qh_base = smem_u32(Qh), ql_base = smem_u32(Ql);
    const uint32_t kh_base = smem_u32(Kh), kl_base = smem_u32(Kl);
    const uint32_t vh_base = smem_u32(Vh), vl_base = smem_u32(Vl);

    // ---- load + split Q tile (128 x 64), row-major padded ----
    {
        const int row = tid >> 1, half = tid & 1;
        const float4* Qg = (const float4*)&g_q[(size_t)(b * TT + q0 + row) * CC +
                                               h * DHD + half * 32];
        const int sb = row * ROWA + half * 32;
#pragma unroll
        for (int j = 0; j < 8; j++) {
            float4 v = Qg[j];
            uint32_t h01, l01, h23, l23;
            split2(v.x, v.y, h01, l01);
            split2(v.z, v.w, h23, l23);
            *(uint32_t*)&Qh[sb + j * 4 + 0] = h01;
            *(uint32_t*)&Qh[sb + j * 4 + 2] = h23;
            *(uint32_t*)&Ql[sb + j * 4 + 0] = l01;
            *(uint32_t*)&Ql[sb + j * 4 + 2] = l23;
        }
    }
    __syncthreads();

    // ---- Q hi fragments persistent in registers; lo re-loaded per tile ----
    const uint32_t qaoff = (uint32_t)((w * 16 + (lane & 15)) * ROWA_B +
                                      ((lane >> 4) << 4));
    uint32_t qf_h[4][4];
#pragma unroll
    for (int ks = 0; ks < 4; ks++)
        LDSM_X4(qf_h[ks][0], qf_h[ks][1], qf_h[ks][2], qf_h[ks][3],
                qh_base + qaoff + ks * 32);

    float oacc[8][4];
#pragma unroll
    for (int jd = 0; jd < 8; jd++)
#pragma unroll
        for (int e = 0; e < 4; e++) oacc[jd][e] = 0.f;
    float m0i = -INFINITY, m1i = -INFINITY, l0i = 0.f, l1i = 0.f;

    for (int kt = 0; kt < TT / 64; kt++) {
        __syncthreads();  // prior readers of K/V smem done
        // ---- load + split K, V tiles (64 x 64) ----
        {
            const int row = tid >> 2, qq = tid & 3;
            const size_t gb = (size_t)(b * TT + kt * 64 + row) * CC + h * DHD + qq * 16;
            const float4* Kg = (const float4*)&g_k[gb];
            const float4* Vg = (const float4*)&g_v[gb];
            const int sb = row * ROWA + qq * 16;
#pragma unroll
            for (int j = 0; j < 4; j++) {
                float4 v = Kg[j];
                uint32_t h01, l01, h23, l23;
                split2(v.x, v.y, h01, l01);
                split2(v.z, v.w, h23, l23);
                *(uint32_t*)&Kh[sb + j * 4 + 0] = h01;
                *(uint32_t*)&Kh[sb + j * 4 + 2] = h23;
                *(uint32_t*)&Kl[sb + j * 4 + 0] = l01;
                *(uint32_t*)&Kl[sb + j * 4 + 2] = l23;
                v = Vg[j];
                split2(v.x, v.y, h01, l01);
                split2(v.z, v.w, h23, l23);
                *(uint32_t*)&Vh[sb + j * 4 + 0] = h01;
                *(uint32_t*)&Vh[sb + j * 4 + 2] = h23;
                *(uint32_t*)&Vl[sb + j * 4 + 0] = l01;
                *(uint32_t*)&Vl[sb + j * 4 + 2] = l23;
            }
        }
        if (tid < 64) {
            float xv = x[(size_t)(b * TT + kt * 64 + tid) * CC];
            kval[tid] = (xv != 0.0f) ? 0.f : -INFINITY;
        }
        __syncthreads();

        // ---- S = Q K^T (3-term compensated), per warp 16x64 ----
        float sacc[8][4];
#pragma unroll
        for (int j = 0; j < 8; j++)
#pragma unroll
            for (int e = 0; e < 4; e++) sacc[j][e] = 0.f;

#pragma unroll
        for (int ks = 0; ks < 4; ks++) {
            uint32_t qf_l[4];
            LDSM_X4(qf_l[0], qf_l[1], qf_l[2], qf_l[3],
                    ql_base + qaoff + ks * 32);
#pragma unroll
            for (int j = 0; j < 8; j++) {
                uint32_t boff = (uint32_t)((j * 8 + (lane & 7)) * ROWA_B +
                                           (((lane >> 3) & 1) << 4) + ks * 32);
                uint32_t bh2[2], bl2[2];
                LDSM_X2(bh2[0], bh2[1], kh_base + boff);
                LDSM_X2(bl2[0], bl2[1], kl_base + boff);
                MMA_BF16(sacc[j], qf_h[ks], bh2);
                MMA_BF16(sacc[j], qf_h[ks], bl2);
                MMA_BF16(sacc[j], qf_l, bh2);
            }
        }

        // ---- scale + mask ----
#pragma unroll
        for (int j = 0; j < 8; j++) {
            float km0 = kval[j * 8 + 2 * qc];
            float km1 = kval[j * 8 + 2 * qc + 1];
            sacc[j][0] = sacc[j][0] * 0.125f + km0;
            sacc[j][1] = sacc[j][1] * 0.125f + km1;
            sacc[j][2] = sacc[j][2] * 0.125f + km0;
            sacc[j][3] = sacc[j][3] * 0.125f + km1;
        }

        // ---- online softmax (rows g, g+8; 4 lanes per row group) ----
        float mx0 = -INFINITY, mx1 = -INFINITY;
#pragma unroll
        for (int j = 0; j < 8; j++) {
            mx0 = fmaxf(mx0, fmaxf(sacc[j][0], sacc[j][1]));
            mx1 = fmaxf(mx1, fmaxf(sacc[j][2], sacc[j][3]));
        }
        mx0 = fmaxf(mx0, __shfl_xor_sync(0xffffffffu, mx0, 1));
        mx0 = fmaxf(mx0, __shfl_xor_sync(0xffffffffu, mx0, 2));
        mx1 = fmaxf(mx1, __shfl_xor_sync(0xffffffffu, mx1, 1));
        mx1 = fmaxf(mx1, __shfl_xor_sync(0xffffffffu, mx1, 2));
        float mn0 = fmaxf(m0i, mx0), mn1 = fmaxf(m1i, mx1);
        float esc0 = __expf(m0i - mn0), esc1 = __expf(m1i - mn1);
        float rs0 = 0.f, rs1 = 0.f;
#pragma unroll
        for (int j = 0; j < 8; j++) {
            float p0 = __expf(sacc[j][0] - mn0);
            float p1 = __expf(sacc[j][1] - mn0);
            float p2 = __expf(sacc[j][2] - mn1);
            float p3 = __expf(sacc[j][3] - mn1);
            sacc[j][0] = p0; sacc[j][1] = p1; sacc[j][2] = p2; sacc[j][3] = p3;
            rs0 += p0 + p1;
            rs1 += p2 + p3;
        }
        rs0 += __shfl_xor_sync(0xffffffffu, rs0, 1);
        rs0 += __shfl_xor_sync(0xffffffffu, rs0, 2);
        rs1 += __shfl_xor_sync(0xffffffffu, rs1, 1);
        rs1 += __shfl_xor_sync(0xffffffffu, rs1, 2);
        l0i = l0i * esc0 + rs0;
        l1i = l1i * esc1 + rs1;
        m0i = mn0; m1i = mn1;
#pragma unroll
        for (int jd = 0; jd < 8; jd++) {
            oacc[jd][0] *= esc0; oacc[jd][1] *= esc0;
            oacc[jd][2] *= esc1; oacc[jd][3] *= esc1;
        }

        // ---- P -> bf16 hi/lo A fragments (register-only conversion) ----
        uint32_t pf_h[4][4], pf_l[4][4];
#pragma unroll
        for (int ks = 0; ks < 4; ks++) {
            int j0 = 2 * ks, j1 = 2 * ks + 1;
            split2(sacc[j0][0], sacc[j0][1], pf_h[ks][0], pf_l[ks][0]);
            split2(sacc[j0][2], sacc[j0][3], pf_h[ks][1], pf_l[ks][1]);
            split2(sacc[j1][0], sacc[j1][1], pf_h[ks][2], pf_l[ks][2]);
            split2(sacc[j1][2], sacc[j1][3], pf_h[ks][3], pf_l[ks][3]);
        }

        // ---- O += P V (3-term compensated); V via ldmatrix.trans ----
#pragma unroll
        for (int jd = 0; jd < 8; jd++) {
#pragma unroll
            for (int ks = 0; ks < 4; ks++) {
                uint32_t boff = (uint32_t)((ks * 16 + (lane & 15)) * ROWA_B + jd * 16);
                uint32_t bvh[2], bvl[2];
                LDSM_X2_T(bvh[0], bvh[1], vh_base + boff);
                LDSM_X2_T(bvl[0], bvl[1], vl_base + boff);
                MMA_BF16(oacc[jd], pf_h[ks], bvh);
                MMA_BF16(oacc[jd], pf_h[ks], bvl);
                MMA_BF16(oacc[jd], pf_l[ks], bvh);
            }
        }
    }

    // ---- epilogue: normalize + store ----
    float inv0 = 1.f / l0i, inv1 = 1.f / l1i;
    const int r0 = q0 + w * 16 + g;
    const size_t obase = (size_t)(b * TT + r0) * CC + h * DHD;
#pragma unroll
    for (int jd = 0; jd < 8; jd++) {
        int col = jd * 8 + 2 * qc;
        *(float2*)&attout[obase + col] =
            make_float2(oacc[jd][0] * inv0, oacc[jd][1] * inv0);
        *(float2*)&attout[obase + 8 * CC + col] =
            make_float2(oacc[jd][2] * inv1, oacc[jd][3] * inv1);
    }
}

// ---------------------------------------------------------------------------
extern "C" void kernel_launch(void* const* d_in, const int* in_sizes, int n_in,
                              void* d_out, int out_size) {
    const float* x   = (const float*)d_in[0];
    const float* wq  = (const float*)d_in[1];
    const float* bq  = (const float*)d_in[2];
    const float* wk  = (const float*)d_in[3];
    const float* bk  = (const float*)d_in[4];
    const float* wv  = (const float*)d_in[5];
    const float* bv  = (const float*)d_in[6];
    const float* wo  = (const float*)d_in[7];
    const float* bo  = (const float*)d_in[8];
    float* out = (float*)d_out;

    float *pq, *pk, *pv, *patt;
    cudaGetSymbolAddress((void**)&pq, g_q);
    cudaGetSymbolAddress((void**)&pk, g_k);
    cudaGetSymbolAddress((void**)&pv, g_v);
    cudaGetSymbolAddress((void**)&patt, g_att);

    const int attn_smem = (128 + 64 + 64) * ROWA * 2 * 2;  // 73,728 B
    cudaFuncSetAttribute(attn_tc, cudaFuncAttributeMaxDynamicSharedMemorySize,
                         attn_smem);

    dim3 gblk(256);
    dim3 ggrid(CC / 128, MTOT / 128);  // (8, 32)

    gemm_nt_tc<<<ggrid, gblk>>>(x, wq, bq, pq, MTOT, CC, CC);
    gemm_nt_tc<<<ggrid, gblk>>>(x, wk, bk, pk, MTOT, CC, CC);
    gemm_nt_tc<<<ggrid, gblk>>>(x, wv, bv, pv, MTOT, CC, CC);

    dim3 agrid(TT / 128, BB * HH);  // (16, 32)
    attn_tc<<<agrid, 256, attn_smem>>>(x, patt);

    gemm_nt_tc<<<ggrid, gblk>>>(patt, wo, bo, out, MTOT, CC, CC);
}

// round 12
// speedup vs baseline: 3.1807x; 1.1814x over previous
#include <cuda_runtime.h>
#include <cuda_bf16.h>
#include <stdint.h>
#include <math.h>

#define BB 2
#define TT 2048
#define CC 1024
#define HH 16
#define DHD 64
#define MTOT (BB*TT)

// ---- GEMM smem layout: 2 stages x 4 arrays x 128 rows x 40 bf16 (80B rows) ----
#define GROW_B 80
#define GAR (128 * GROW_B)     // 10240 B per array per stage
#define GSTG (4 * GAR)         // 40960 B per stage
#define GSMEM (2 * GSTG)       // 81920 B

// ---- Attention smem: Q (2 arrays x 128 x 144B) + KV 2 stages x 4 arrays x 64 x 144B ----
#define AROW_B 144
#define QAR (128 * AROW_B)     // 18432
#define KAR (64 * AROW_B)      // 9216
#define KVSTG (4 * KAR)        // 36864
#define ASMEM (2 * QAR + 2 * KVSTG)  // 110592

// ---- scratch (no allocation allowed) ----
__device__ __nv_bfloat16 g_xh[MTOT * CC], g_xl[MTOT * CC];
__device__ __nv_bfloat16 g_wqh[CC * CC], g_wql[CC * CC];
__device__ __nv_bfloat16 g_wkh[CC * CC], g_wkl[CC * CC];
__device__ __nv_bfloat16 g_wvh[CC * CC], g_wvl[CC * CC];
__device__ __nv_bfloat16 g_woh[CC * CC], g_wol[CC * CC];
__device__ __nv_bfloat16 g_qh[MTOT * CC], g_ql[MTOT * CC];
__device__ __nv_bfloat16 g_kh[MTOT * CC], g_kl[MTOT * CC];
__device__ __nv_bfloat16 g_vh[MTOT * CC], g_vl[MTOT * CC];
__device__ __nv_bfloat16 g_ph[MTOT * CC], g_pl[MTOT * CC];
__device__ float g_mask[MTOT];

__device__ __forceinline__ uint32_t smem_u32(const void* p) {
    return (uint32_t)__cvta_generic_to_shared(p);
}

#define LDSM_X4(r0, r1, r2, r3, addr)                                          \
    asm volatile("ldmatrix.sync.aligned.m8n8.x4.shared.b16 {%0,%1,%2,%3}, [%4];" \
                 : "=r"(r0), "=r"(r1), "=r"(r2), "=r"(r3) : "r"(addr))
#define LDSM_X2(r0, r1, addr)                                                  \
    asm volatile("ldmatrix.sync.aligned.m8n8.x2.shared.b16 {%0,%1}, [%2];"     \
                 : "=r"(r0), "=r"(r1) : "r"(addr))
#define LDSM_X2_T(r0, r1, addr)                                                \
    asm volatile("ldmatrix.sync.aligned.m8n8.x2.trans.shared.b16 {%0,%1}, [%2];" \
                 : "=r"(r0), "=r"(r1) : "r"(addr))

#define MMA_BF16(d, a, b)                                                      \
    asm volatile("mma.sync.aligned.m16n8k16.row.col.f32.bf16.bf16.f32 "        \
                 "{%0,%1,%2,%3}, {%4,%5,%6,%7}, {%8,%9}, {%0,%1,%2,%3};"       \
                 : "+f"((d)[0]), "+f"((d)[1]), "+f"((d)[2]), "+f"((d)[3])      \
                 : "r"((a)[0]), "r"((a)[1]), "r"((a)[2]), "r"((a)[3]),         \
                   "r"((b)[0]), "r"((b)[1]))

#define CP_ASYNC16(saddr, gaddr)                                               \
    asm volatile("cp.async.cg.shared.global [%0], [%1], 16;"                   \
                 :: "r"(saddr), "l"(gaddr))
#define CP_COMMIT  asm volatile("cp.async.commit_group;")
#define CP_WAIT0   asm volatile("cp.async.wait_group 0;")
#define CP_WAIT1   asm volatile("cp.async.wait_group 1;")

// split fp32 pair -> packed bf16 hi + packed bf16 residual
__device__ __forceinline__ void split2(float a, float b, uint32_t& hi, uint32_t& lo) {
    __nv_bfloat162 h = __float22bfloat162_rn(make_float2(a, b));
    float2 hf = __bfloat1622float2(h);
    __nv_bfloat162 l = __float22bfloat162_rn(make_float2(a - hf.x, b - hf.y));
    hi = *reinterpret_cast<uint32_t*>(&h);
    lo = *reinterpret_cast<uint32_t*>(&l);
}

// ---------------------------------------------------------------------------
// elementwise fp32 -> bf16 hi/lo split (n4 float4 elements)
// ---------------------------------------------------------------------------
__global__ void split_f32(const float* __restrict__ in,
                          __nv_bfloat16* __restrict__ oh,
                          __nv_bfloat16* __restrict__ ol, int n4) {
    int i = blockIdx.x * blockDim.x + threadIdx.x;
    if (i < n4) {
        float4 v = ((const float4*)in)[i];
        uint32_t h01, l01, h23, l23;
        split2(v.x, v.y, h01, l01);
        split2(v.z, v.w, h23, l23);
        ((uint32_t*)oh)[i * 2] = h01;
        ((uint32_t*)oh)[i * 2 + 1] = h23;
        ((uint32_t*)ol)[i * 2] = l01;
        ((uint32_t*)ol)[i * 2 + 1] = l23;
    }
}

__global__ void mask_kernel(const float* __restrict__ x, float* __restrict__ mask) {
    int i = blockIdx.x * blockDim.x + threadIdx.x;
    if (i < MTOT) mask[i] = (x[(size_t)i * CC] != 0.0f) ? 0.f : -INFINITY;
}

// ---------------------------------------------------------------------------
// bf16-input NT GEMM, 3-term compensated, cp.async double-buffered.
//   out[m,n] = sum_k (Ah+Al)[m,k]*(Bh+Bl)[n,k] + bias[n]
// out_split=1: write split bf16 (outh/outl); else write fp32 (outf).
// ---------------------------------------------------------------------------
__global__ __launch_bounds__(256) void gemm_bf16_tc(
    const __nv_bfloat16* __restrict__ Ah, const __nv_bfloat16* __restrict__ Al,
    const __nv_bfloat16* __restrict__ Bh, const __nv_bfloat16* __restrict__ Bl,
    const float* __restrict__ bias, float* __restrict__ outf,
    __nv_bfloat16* __restrict__ outh, __nv_bfloat16* __restrict__ outl,
    int M, int N, int K, int out_split) {
    extern __shared__ char sgc[];
    const uint32_t sbase = smem_u32(sgc);
    const int tid = threadIdx.x;
    const int wid = tid >> 5, lane = tid & 31;
    const int warp_m = wid >> 2, warp_n = wid & 3;
    const int m0 = blockIdx.y * 128, n0 = blockIdx.x * 128;

    float acc[4][4][4];
#pragma unroll
    for (int mt = 0; mt < 4; mt++)
#pragma unroll
        for (int nt = 0; nt < 4; nt++)
#pragma unroll
            for (int e = 0; e < 4; e++) acc[mt][nt][e] = 0.f;

    uint32_t a_off[4], b_off[4];
#pragma unroll
    for (int mt = 0; mt < 4; mt++)
        a_off[mt] = (uint32_t)((warp_m * 64 + mt * 16 + (lane & 15)) * GROW_B +
                               ((lane >> 4) << 4));
#pragma unroll
    for (int nt = 0; nt < 4; nt++)
        b_off[nt] = (uint32_t)((warp_n * 32 + nt * 8 + (lane & 7)) * GROW_B +
                               (((lane >> 3) & 1) << 4));

    auto issue = [&](int k0, int s) {
#pragma unroll
        for (int t = 0; t < 8; t++) {
            int idx = tid + t * 256;
            int a = idx >> 9, loc = idx & 511;
            int r = loc >> 2, cc = loc & 3;
            const __nv_bfloat16* gp = (a == 0) ? Ah : (a == 1) ? Al
                                     : (a == 2) ? Bh : Bl;
            int row = ((a < 2) ? m0 : n0) + r;
            CP_ASYNC16(sbase + s * GSTG + a * GAR + r * GROW_B + cc * 16,
                       gp + (size_t)row * K + k0 + cc * 8);
        }
        CP_COMMIT;
    };

    const int NIT = K / 32;
    issue(0, 0);
    for (int it = 0; it < NIT; it++) {
        if (it + 1 < NIT) {
            issue((it + 1) * 32, (it + 1) & 1);
            CP_WAIT1;
        } else {
            CP_WAIT0;
        }
        __syncthreads();

        const uint32_t stg = sbase + (it & 1) * GSTG;
#pragma unroll
        for (int term = 0; term < 3; term++) {
            uint32_t abase = stg + ((term == 2) ? GAR : 0);
            uint32_t bbase = stg + 2 * GAR + ((term == 1) ? GAR : 0);
#pragma unroll
            for (int ks = 0; ks < 2; ks++) {
                uint32_t af[4][4], bf[4][2];
#pragma unroll
                for (int mt = 0; mt < 4; mt++)
                    LDSM_X4(af[mt][0], af[mt][1], af[mt][2], af[mt][3],
                            abase + a_off[mt] + ks * 32);
#pragma unroll
                for (int nt = 0; nt < 4; nt++)
                    LDSM_X2(bf[nt][0], bf[nt][1], bbase + b_off[nt] + ks * 32);
#pragma unroll
                for (int mt = 0; mt < 4; mt++)
#pragma unroll
                    for (int nt = 0; nt < 4; nt++)
                        MMA_BF16(acc[mt][nt], af[mt], bf[nt]);
            }
        }
        __syncthreads();
    }

    const int g = lane >> 2, c = lane & 3;
#pragma unroll
    for (int nt = 0; nt < 4; nt++) {
        int col = n0 + warp_n * 32 + nt * 8 + c * 2;
        float b0 = bias[col], b1 = bias[col + 1];
#pragma unroll
        for (int mt = 0; mt < 4; mt++) {
            int row = m0 + warp_m * 64 + mt * 16 + g;
            float v00 = acc[mt][nt][0] + b0, v01 = acc[mt][nt][1] + b1;
            float v10 = acc[mt][nt][2] + b0, v11 = acc[mt][nt][3] + b1;
            if (out_split) {
                uint32_t hi, lo;
                split2(v00, v01, hi, lo);
                *(uint32_t*)&outh[(size_t)row * N + col] = hi;
                *(uint32_t*)&outl[(size_t)row * N + col] = lo;
                split2(v10, v11, hi, lo);
                *(uint32_t*)&outh[(size_t)(row + 8) * N + col] = hi;
                *(uint32_t*)&outl[(size_t)(row + 8) * N + col] = lo;
            } else {
                *(float2*)&outf[(size_t)row * N + col] = make_float2(v00, v01);
                *(float2*)&outf[(size_t)(row + 8) * N + col] = make_float2(v10, v11);
            }
        }
    }
}

// ---------------------------------------------------------------------------
// Tensor-core flash attention on pre-split bf16 q/k/v, cp.async double-buffered
// K/V. CTA: 128 q-rows x (b,h); 8 warps x 16 q-rows. Output: split bf16.
// ---------------------------------------------------------------------------
__global__ __launch_bounds__(256, 2) void attn_tc(
    const __nv_bfloat16* __restrict__ qh, const __nv_bfloat16* __restrict__ ql,
    const __nv_bfloat16* __restrict__ kh, const __nv_bfloat16* __restrict__ kl,
    const __nv_bfloat16* __restrict__ vh, const __nv_bfloat16* __restrict__ vl,
    const float* __restrict__ mask,
    __nv_bfloat16* __restrict__ ph, __nv_bfloat16* __restrict__ pl) {
    extern __shared__ char sac[];
    const uint32_t sbase = smem_u32(sac);
    const uint32_t kvb = sbase + 2 * QAR;

    const int tid = threadIdx.x;
    const int w = tid >> 5, lane = tid & 31;
    const int g = lane >> 2, qc = lane & 3;
    const int bh = blockIdx.y;
    const int b = bh / HH, h = bh % HH;
    const int q0 = blockIdx.x * 128;

    auto issue_kv = [&](int kt, int s) {
#pragma unroll
        for (int t = 0; t < 8; t++) {
            int idx = tid + t * 256;
            int a = idx >> 9, loc = idx & 511;
            int r = loc >> 3, cc = loc & 7;
            const __nv_bfloat16* gp = (a == 0) ? kh : (a == 1) ? kl
                                     : (a == 2) ? vh : vl;
            CP_ASYNC16(kvb + s * KVSTG + a * KAR + r * AROW_B + cc * 16,
                       gp + (size_t)(b * TT + kt * 64 + r) * CC + h * DHD + cc * 8);
        }
        CP_COMMIT;
    };

    // ---- preamble: Q (both arrays) + KV tile 0 ----
    {
#pragma unroll
        for (int t = 0; t < 8; t++) {
            int idx = tid + t * 256;
            int a = idx >> 10, loc = idx & 1023;
            int r = loc >> 3, cc = loc & 7;
            const __nv_bfloat16* gp = a ? ql : qh;
            CP_ASYNC16(sbase + a * QAR + r * AROW_B + cc * 16,
                       gp + (size_t)(b * TT + q0 + r) * CC + h * DHD + cc * 8);
        }
        CP_COMMIT;
    }
    issue_kv(0, 0);
    CP_WAIT0;
    __syncthreads();

    // ---- Q hi fragments persistent; lo re-loaded per tile ----
    const uint32_t qaoff = (uint32_t)((w * 16 + (lane & 15)) * AROW_B +
                                      ((lane >> 4) << 4));
    uint32_t qf_h[4][4];
#pragma unroll
    for (int ks = 0; ks < 4; ks++)
        LDSM_X4(qf_h[ks][0], qf_h[ks][1], qf_h[ks][2], qf_h[ks][3],
                sbase + qaoff + ks * 32);

    float oacc[8][4];
#pragma unroll
    for (int jd = 0; jd < 8; jd++)
#pragma unroll
        for (int e = 0; e < 4; e++) oacc[jd][e] = 0.f;
    float m0i = -INFINITY, m1i = -INFINITY, l0i = 0.f, l1i = 0.f;

    const int NT = TT / 64;
    for (int kt = 0; kt < NT; kt++) {
        if (kt + 1 < NT) {
            issue_kv(kt + 1, (kt + 1) & 1);
            CP_WAIT1;
        } else {
            CP_WAIT0;
        }
        __syncthreads();

        const uint32_t kh_b = kvb + (kt & 1) * KVSTG;
        const uint32_t kl_b = kh_b + KAR;
        const uint32_t vh_b = kh_b + 2 * KAR;
        const uint32_t vl_b = kh_b + 3 * KAR;

        // ---- S = Q K^T (3-term compensated) ----
        float sacc[8][4];
#pragma unroll
        for (int j = 0; j < 8; j++)
#pragma unroll
            for (int e = 0; e < 4; e++) sacc[j][e] = 0.f;

#pragma unroll
        for (int ks = 0; ks < 4; ks++) {
            uint32_t qf_l[4];
            LDSM_X4(qf_l[0], qf_l[1], qf_l[2], qf_l[3],
                    sbase + QAR + qaoff + ks * 32);
#pragma unroll
            for (int j = 0; j < 8; j++) {
                uint32_t boff = (uint32_t)((j * 8 + (lane & 7)) * AROW_B +
                                           (((lane >> 3) & 1) << 4) + ks * 32);
                uint32_t bh2[2], bl2[2];
                LDSM_X2(bh2[0], bh2[1], kh_b + boff);
                LDSM_X2(bl2[0], bl2[1], kl_b + boff);
                MMA_BF16(sacc[j], qf_h[ks], bh2);
                MMA_BF16(sacc[j], qf_h[ks], bl2);
                MMA_BF16(sacc[j], qf_l, bh2);
            }
        }

        // ---- scale + mask (mask: L1-hot global array) ----
        const float* mrow = &mask[b * TT + kt * 64];
#pragma unroll
        for (int j = 0; j < 8; j++) {
            float km0 = mrow[j * 8 + 2 * qc];
            float km1 = mrow[j * 8 + 2 * qc + 1];
            sacc[j][0] = sacc[j][0] * 0.125f + km0;
            sacc[j][1] = sacc[j][1] * 0.125f + km1;
            sacc[j][2] = sacc[j][2] * 0.125f + km0;
            sacc[j][3] = sacc[j][3] * 0.125f + km1;
        }

        // ---- online softmax ----
        float mx0 = -INFINITY, mx1 = -INFINITY;
#pragma unroll
        for (int j = 0; j < 8; j++) {
            mx0 = fmaxf(mx0, fmaxf(sacc[j][0], sacc[j][1]));
            mx1 = fmaxf(mx1, fmaxf(sacc[j][2], sacc[j][3]));
        }
        mx0 = fmaxf(mx0, __shfl_xor_sync(0xffffffffu, mx0, 1));
        mx0 = fmaxf(mx0, __shfl_xor_sync(0xffffffffu, mx0, 2));
        mx1 = fmaxf(mx1, __shfl_xor_sync(0xffffffffu, mx1, 1));
        mx1 = fmaxf(mx1, __shfl_xor_sync(0xffffffffu, mx1, 2));
        float mn0 = fmaxf(m0i, mx0), mn1 = fmaxf(m1i, mx1);
        float esc0 = __expf(m0i - mn0), esc1 = __expf(m1i - mn1);
        float rs0 = 0.f, rs1 = 0.f;
#pragma unroll
        for (int j = 0; j < 8; j++) {
            float p0 = __expf(sacc[j][0] - mn0);
            float p1 = __expf(sacc[j][1] - mn0);
            float p2 = __expf(sacc[j][2] - mn1);
            float p3 = __expf(sacc[j][3] - mn1);
            sacc[j][0] = p0; sacc[j][1] = p1; sacc[j][2] = p2; sacc[j][3] = p3;
            rs0 += p0 + p1;
            rs1 += p2 + p3;
        }
        rs0 += __shfl_xor_sync(0xffffffffu, rs0, 1);
        rs0 += __shfl_xor_sync(0xffffffffu, rs0, 2);
        rs1 += __shfl_xor_sync(0xffffffffu, rs1, 1);
        rs1 += __shfl_xor_sync(0xffffffffu, rs1, 2);
        l0i = l0i * esc0 + rs0;
        l1i = l1i * esc1 + rs1;
        m0i = mn0; m1i = mn1;
#pragma unroll
        for (int jd = 0; jd < 8; jd++) {
            oacc[jd][0] *= esc0; oacc[jd][1] *= esc0;
            oacc[jd][2] *= esc1; oacc[jd][3] *= esc1;
        }

        // ---- P -> bf16 hi/lo A fragments (register-only) ----
        uint32_t pf_h[4][4], pf_l[4][4];
#pragma unroll
        for (int ks = 0; ks < 4; ks++) {
            int j0 = 2 * ks, j1 = 2 * ks + 1;
            split2(sacc[j0][0], sacc[j0][1], pf_h[ks][0], pf_l[ks][0]);
            split2(sacc[j0][2], sacc[j0][3], pf_h[ks][1], pf_l[ks][1]);
            split2(sacc[j1][0], sacc[j1][1], pf_h[ks][2], pf_l[ks][2]);
            split2(sacc[j1][2], sacc[j1][3], pf_h[ks][3], pf_l[ks][3]);
        }

        // ---- O += P V (3-term); V via ldmatrix.trans ----
#pragma unroll
        for (int jd = 0; jd < 8; jd++) {
#pragma unroll
            for (int ks = 0; ks < 4; ks++) {
                uint32_t boff = (uint32_t)((ks * 16 + (lane & 15)) * AROW_B + jd * 16);
                uint32_t bvh[2], bvl[2];
                LDSM_X2_T(bvh[0], bvh[1], vh_b + boff);
                LDSM_X2_T(bvl[0], bvl[1], vl_b + boff);
                MMA_BF16(oacc[jd], pf_h[ks], bvh);
                MMA_BF16(oacc[jd], pf_h[ks], bvl);
                MMA_BF16(oacc[jd], pf_l[ks], bvh);
            }
        }
        __syncthreads();
    }

    // ---- epilogue: normalize + split-store ----
    float inv0 = 1.f / l0i, inv1 = 1.f / l1i;
    const int r0 = q0 + w * 16 + g;
    const size_t obase = (size_t)(b * TT + r0) * CC + h * DHD;
#pragma unroll
    for (int jd = 0; jd < 8; jd++) {
        int col = jd * 8 + 2 * qc;
        uint32_t hi, lo;
        split2(oacc[jd][0] * inv0, oacc[jd][1] * inv0, hi, lo);
        *(uint32_t*)&ph[obase + col] = hi;
        *(uint32_t*)&pl[obase + col] = lo;
        split2(oacc[jd][2] * inv1, oacc[jd][3] * inv1, hi, lo);
        *(uint32_t*)&ph[obase + 8 * CC + col] = hi;
        *(uint32_t*)&pl[obase + 8 * CC + col] = lo;
    }
}

// ---------------------------------------------------------------------------
extern "C" void kernel_launch(void* const* d_in, const int* in_sizes, int n_in,
                              void* d_out, int out_size) {
    const float* x   = (const float*)d_in[0];
    const float* wq  = (const float*)d_in[1];
    const float* bq  = (const float*)d_in[2];
    const float* wk  = (const float*)d_in[3];
    const float* bk  = (const float*)d_in[4];
    const float* wv  = (const float*)d_in[5];
    const float* bv  = (const float*)d_in[6];
    const float* wo  = (const float*)d_in[7];
    const float* bo  = (const float*)d_in[8];
    float* out = (float*)d_out;

    __nv_bfloat16 *xh, *xl, *wqh, *wql, *wkh, *wkl, *wvh, *wvl, *woh, *wol;
    __nv_bfloat16 *qh, *ql, *kh, *kl, *vh, *vl, *ph, *pl;
    float* maskp;
    cudaGetSymbolAddress((void**)&xh, g_xh);   cudaGetSymbolAddress((void**)&xl, g_xl);
    cudaGetSymbolAddress((void**)&wqh, g_wqh); cudaGetSymbolAddress((void**)&wql, g_wql);
    cudaGetSymbolAddress((void**)&wkh, g_wkh); cudaGetSymbolAddress((void**)&wkl, g_wkl);
    cudaGetSymbolAddress((void**)&wvh, g_wvh); cudaGetSymbolAddress((void**)&wvl, g_wvl);
    cudaGetSymbolAddress((void**)&woh, g_woh); cudaGetSymbolAddress((void**)&wol, g_wol);
    cudaGetSymbolAddress((void**)&qh, g_qh);   cudaGetSymbolAddress((void**)&ql, g_ql);
    cudaGetSymbolAddress((void**)&kh, g_kh);   cudaGetSymbolAddress((void**)&kl, g_kl);
    cudaGetSymbolAddress((void**)&vh, g_vh);   cudaGetSymbolAddress((void**)&vl, g_vl);
    cudaGetSymbolAddress((void**)&ph, g_ph);   cudaGetSymbolAddress((void**)&pl, g_pl);
    cudaGetSymbolAddress((void**)&maskp, g_mask);

    cudaFuncSetAttribute(gemm_bf16_tc, cudaFuncAttributeMaxDynamicSharedMemorySize,
                         GSMEM);
    cudaFuncSetAttribute(attn_tc, cudaFuncAttributeMaxDynamicSharedMemorySize,
                         ASMEM);

    // ---- pre-split inputs ----
    int n4x = MTOT * CC / 4;
    int n4w = CC * CC / 4;
    split_f32<<<(n4x + 255) / 256, 256>>>(x, xh, xl, n4x);
    split_f32<<<(n4w + 255) / 256, 256>>>(wq, wqh, wql, n4w);
    split_f32<<<(n4w + 255) / 256, 256>>>(wk, wkh, wkl, n4w);
    split_f32<<<(n4w + 255) / 256, 256>>>(wv, wvh, wvl, n4w);
    split_f32<<<(n4w + 255) / 256, 256>>>(wo, woh, wol, n4w);
    mask_kernel<<<(MTOT + 255) / 256, 256>>>(x, maskp);

    dim3 gblk(256);
    dim3 ggrid(CC / 128, MTOT / 128);  // (8, 32)

    gemm_bf16_tc<<<ggrid, gblk, GSMEM>>>(xh, xl, wqh, wql, bq, nullptr, qh, ql,
                                         MTOT, CC, CC, 1);
    gemm_bf16_tc<<<ggrid, gblk, GSMEM>>>(xh, xl, wkh, wkl, bk, nullptr, kh, kl,
                                         MTOT, CC, CC, 1);
    gemm_bf16_tc<<<ggrid, gblk, GSMEM>>>(xh, xl, wvh, wvl, bv, nullptr, vh, vl,
                                         MTOT, CC, CC, 1);

    dim3 agrid(TT / 128, BB * HH);  // (16, 32)
    attn_tc<<<agrid, 256, ASMEM>>>(qh, ql, kh, kl, vh, vl, maskp, ph, pl);

    gemm_bf16_tc<<<ggrid, gblk, GSMEM>>>(ph, pl, woh, wol, bo, out, nullptr, nullptr,
                                         MTOT, CC, CC, 0);
}

// round 13
// speedup vs baseline: 3.3310x; 1.0472x over previous
#include <cuda_runtime.h>
#include <cuda_bf16.h>
#include <stdint.h>
#include <math.h>

#define BB 2
#define TT 2048
#define CC 1024
#define HH 16
#define DHD 64
#define MTOT (BB*TT)

// ---- GEMM smem layout: 2 stages x 4 arrays x 128 rows x 40 bf16 (80B rows) ----
#define GROW_B 80
#define GAR (128 * GROW_B)     // 10240 B per array per stage
#define GSTG (4 * GAR)         // 40960 B per stage
#define GSMEM (2 * GSTG)       // 81920 B

// ---- Attention smem: Q (2 arrays x 128 x 144B) + KV 2 stages x 4 arrays x 64 x 144B ----
#define AROW_B 144
#define QAR (128 * AROW_B)     // 18432
#define KAR (64 * AROW_B)      // 9216
#define KVSTG (4 * KAR)        // 36864
#define ASMEM (2 * QAR + 2 * KVSTG)  // 110592

// ---- scratch (no allocation allowed) ----
__device__ __nv_bfloat16 g_xh[MTOT * CC], g_xl[MTOT * CC];
__device__ __nv_bfloat16 g_wqh[CC * CC], g_wql[CC * CC];
__device__ __nv_bfloat16 g_wkh[CC * CC], g_wkl[CC * CC];
__device__ __nv_bfloat16 g_wvh[CC * CC], g_wvl[CC * CC];
__device__ __nv_bfloat16 g_woh[CC * CC], g_wol[CC * CC];
__device__ __nv_bfloat16 g_qh[MTOT * CC], g_ql[MTOT * CC];
__device__ __nv_bfloat16 g_kh[MTOT * CC], g_kl[MTOT * CC];
__device__ __nv_bfloat16 g_vh[MTOT * CC], g_vl[MTOT * CC];
__device__ __nv_bfloat16 g_ph[MTOT * CC], g_pl[MTOT * CC];
__device__ float g_mask[MTOT];

__device__ __forceinline__ uint32_t smem_u32(const void* p) {
    return (uint32_t)__cvta_generic_to_shared(p);
}

#define LDSM_X4(r0, r1, r2, r3, addr)                                          \
    asm volatile("ldmatrix.sync.aligned.m8n8.x4.shared.b16 {%0,%1,%2,%3}, [%4];" \
                 : "=r"(r0), "=r"(r1), "=r"(r2), "=r"(r3) : "r"(addr))
#define LDSM_X4_T(r0, r1, r2, r3, addr)                                        \
    asm volatile("ldmatrix.sync.aligned.m8n8.x4.trans.shared.b16 {%0,%1,%2,%3}, [%4];" \
                 : "=r"(r0), "=r"(r1), "=r"(r2), "=r"(r3) : "r"(addr))

#define MMA_BF16(d, a, b)                                                      \
    asm volatile("mma.sync.aligned.m16n8k16.row.col.f32.bf16.bf16.f32 "        \
                 "{%0,%1,%2,%3}, {%4,%5,%6,%7}, {%8,%9}, {%0,%1,%2,%3};"       \
                 : "+f"((d)[0]), "+f"((d)[1]), "+f"((d)[2]), "+f"((d)[3])      \
                 : "r"((a)[0]), "r"((a)[1]), "r"((a)[2]), "r"((a)[3]),         \
                   "r"((b)[0]), "r"((b)[1]))

#define CP_ASYNC16(saddr, gaddr)                                               \
    asm volatile("cp.async.cg.shared.global [%0], [%1], 16;"                   \
                 :: "r"(saddr), "l"(gaddr))
#define CP_COMMIT  asm volatile("cp.async.commit_group;")
#define CP_WAIT0   asm volatile("cp.async.wait_group 0;")
#define CP_WAIT1   asm volatile("cp.async.wait_group 1;")

// split fp32 pair -> packed bf16 hi + packed bf16 residual
__device__ __forceinline__ void split2(float a, float b, uint32_t& hi, uint32_t& lo) {
    __nv_bfloat162 h = __float22bfloat162_rn(make_float2(a, b));
    float2 hf = __bfloat1622float2(h);
    __nv_bfloat162 l = __float22bfloat162_rn(make_float2(a - hf.x, b - hf.y));
    hi = *reinterpret_cast<uint32_t*>(&h);
    lo = *reinterpret_cast<uint32_t*>(&l);
}

// ---------------------------------------------------------------------------
// fused preamble: split x + 4 weights into bf16 hi/lo, and build the pad mask.
// index space: [0, 1M) -> x float4s; [1M, 2M) -> weights (256K float4 each).
// ---------------------------------------------------------------------------
#define N4X (MTOT * CC / 4)         // 1048576
#define N4W (CC * CC / 4)           // 262144
__global__ void split_all(const float* __restrict__ x,
                          const float* __restrict__ wq, const float* __restrict__ wk,
                          const float* __restrict__ wv, const float* __restrict__ wo,
                          __nv_bfloat16* __restrict__ xh, __nv_bfloat16* __restrict__ xl,
                          __nv_bfloat16* __restrict__ wqh, __nv_bfloat16* __restrict__ wql,
                          __nv_bfloat16* __restrict__ wkh, __nv_bfloat16* __restrict__ wkl,
                          __nv_bfloat16* __restrict__ wvh, __nv_bfloat16* __restrict__ wvl,
                          __nv_bfloat16* __restrict__ woh, __nv_bfloat16* __restrict__ wol,
                          float* __restrict__ mask) {
    int i = blockIdx.x * blockDim.x + threadIdx.x;
    const float* in;
    __nv_bfloat16 *oh, *ol;
    int j;
    if (i < N4X) {
        in = x; oh = xh; ol = xl; j = i;
    } else {
        int t = i - N4X;
        int w = t >> 18;          // /N4W
        j = t & (N4W - 1);
        if (w == 0)      { in = wq; oh = wqh; ol = wql; }
        else if (w == 1) { in = wk; oh = wkh; ol = wkl; }
        else if (w == 2) { in = wv; oh = wvh; ol = wvl; }
        else             { in = wo; oh = woh; ol = wol; }
    }
    float4 v = ((const float4*)in)[j];
    uint32_t h01, l01, h23, l23;
    split2(v.x, v.y, h01, l01);
    split2(v.z, v.w, h23, l23);
    ((uint32_t*)oh)[j * 2] = h01;
    ((uint32_t*)oh)[j * 2 + 1] = h23;
    ((uint32_t*)ol)[j * 2] = l01;
    ((uint32_t*)ol)[j * 2 + 1] = l23;
    if (i < MTOT) mask[i] = (x[(size_t)i * CC] != 0.0f) ? 0.f : -INFINITY;
}

// ---------------------------------------------------------------------------
// bf16-input NT GEMM, 3-term compensated, cp.async double-buffered.
// B fragments: hi of n-tile pair via single ldmatrix.x4 (2 tiles per instr).
// ---------------------------------------------------------------------------
__global__ __launch_bounds__(256) void gemm_bf16_tc(
    const __nv_bfloat16* __restrict__ Ah, const __nv_bfloat16* __restrict__ Al,
    const __nv_bfloat16* __restrict__ Bh, const __nv_bfloat16* __restrict__ Bl,
    const float* __restrict__ bias, float* __restrict__ outf,
    __nv_bfloat16* __restrict__ outh, __nv_bfloat16* __restrict__ outl,
    int M, int N, int K, int out_split) {
    extern __shared__ char sgc[];
    const uint32_t sbase = smem_u32(sgc);
    const int tid = threadIdx.x;
    const int wid = tid >> 5, lane = tid & 31;
    const int warp_m = wid >> 2, warp_n = wid & 3;
    const int m0 = blockIdx.y * 128, n0 = blockIdx.x * 128;

    float acc[4][4][4];
#pragma unroll
    for (int mt = 0; mt < 4; mt++)
#pragma unroll
        for (int nt = 0; nt < 4; nt++)
#pragma unroll
            for (int e = 0; e < 4; e++) acc[mt][nt][e] = 0.f;

    uint32_t a_off[4], bp_off[2];
#pragma unroll
    for (int mt = 0; mt < 4; mt++)
        a_off[mt] = (uint32_t)((warp_m * 64 + mt * 16 + (lane & 15)) * GROW_B +
                               ((lane >> 4) << 4));
    // n-tile pair p covers nt = 2p + (lane>>4); lanes 0-15 -> nt=2p, 16-31 -> 2p+1
#pragma unroll
    for (int p = 0; p < 2; p++)
        bp_off[p] = (uint32_t)((warp_n * 32 + (2 * p + (lane >> 4)) * 8 + (lane & 7)) *
                                   GROW_B + (((lane >> 3) & 1) << 4));

    auto issue = [&](int k0, int s) {
#pragma unroll
        for (int t = 0; t < 8; t++) {
            int idx = tid + t * 256;
            int a = idx >> 9, loc = idx & 511;
            int r = loc >> 2, cc = loc & 3;
            const __nv_bfloat16* gp = (a == 0) ? Ah : (a == 1) ? Al
                                     : (a == 2) ? Bh : Bl;
            int row = ((a < 2) ? m0 : n0) + r;
            CP_ASYNC16(sbase + s * GSTG + a * GAR + r * GROW_B + cc * 16,
                       gp + (size_t)row * K + k0 + cc * 8);
        }
        CP_COMMIT;
    };

    const int NIT = K / 32;
    issue(0, 0);
    for (int it = 0; it < NIT; it++) {
        if (it + 1 < NIT) {
            issue((it + 1) * 32, (it + 1) & 1);
            CP_WAIT1;
        } else {
            CP_WAIT0;
        }
        __syncthreads();

        const uint32_t stg = sbase + (it & 1) * GSTG;
#pragma unroll
        for (int term = 0; term < 3; term++) {
            uint32_t abase = stg + ((term == 2) ? GAR : 0);
            uint32_t bbase = stg + 2 * GAR + ((term == 1) ? GAR : 0);
#pragma unroll
            for (int ks = 0; ks < 2; ks++) {
                uint32_t af[4][4], bf[4][2];
#pragma unroll
                for (int mt = 0; mt < 4; mt++)
                    LDSM_X4(af[mt][0], af[mt][1], af[mt][2], af[mt][3],
                            abase + a_off[mt] + ks * 32);
#pragma unroll
                for (int p = 0; p < 2; p++)
                    LDSM_X4(bf[2 * p][0], bf[2 * p][1], bf[2 * p + 1][0],
                            bf[2 * p + 1][1], bbase + bp_off[p] + ks * 32);
#pragma unroll
                for (int mt = 0; mt < 4; mt++)
#pragma unroll
                    for (int nt = 0; nt < 4; nt++)
                        MMA_BF16(acc[mt][nt], af[mt], bf[nt]);
            }
        }
        __syncthreads();
    }

    const int g = lane >> 2, c = lane & 3;
#pragma unroll
    for (int nt = 0; nt < 4; nt++) {
        int col = n0 + warp_n * 32 + nt * 8 + c * 2;
        float b0 = bias[col], b1 = bias[col + 1];
#pragma unroll
        for (int mt = 0; mt < 4; mt++) {
            int row = m0 + warp_m * 64 + mt * 16 + g;
            float v00 = acc[mt][nt][0] + b0, v01 = acc[mt][nt][1] + b1;
            float v10 = acc[mt][nt][2] + b0, v11 = acc[mt][nt][3] + b1;
            if (out_split) {
                uint32_t hi, lo;
                split2(v00, v01, hi, lo);
                *(uint32_t*)&outh[(size_t)row * N + col] = hi;
                *(uint32_t*)&outl[(size_t)row * N + col] = lo;
                split2(v10, v11, hi, lo);
                *(uint32_t*)&outh[(size_t)(row + 8) * N + col] = hi;
                *(uint32_t*)&outl[(size_t)(row + 8) * N + col] = lo;
            } else {
                *(float2*)&outf[(size_t)row * N + col] = make_float2(v00, v01);
                *(float2*)&outf[(size_t)(row + 8) * N + col] = make_float2(v10, v11);
            }
        }
    }
}

// ---------------------------------------------------------------------------
// Tensor-core flash attention on pre-split bf16 q/k/v, cp.async double-buffered
// K/V. hi+lo fragments fetched together: lanes 0-15 -> hi array, 16-31 -> lo.
// ---------------------------------------------------------------------------
__global__ __launch_bounds__(256, 2) void attn_tc(
    const __nv_bfloat16* __restrict__ qh, const __nv_bfloat16* __restrict__ ql,
    const __nv_bfloat16* __restrict__ kh, const __nv_bfloat16* __restrict__ kl,
    const __nv_bfloat16* __restrict__ vh, const __nv_bfloat16* __restrict__ vl,
    const float* __restrict__ mask,
    __nv_bfloat16* __restrict__ ph, __nv_bfloat16* __restrict__ pl) {
    extern __shared__ char sac[];
    const uint32_t sbase = smem_u32(sac);
    const uint32_t kvb = sbase + 2 * QAR;

    const int tid = threadIdx.x;
    const int w = tid >> 5, lane = tid & 31;
    const int g = lane >> 2, qc = lane & 3;
    const int bh = blockIdx.y;
    const int b = bh / HH, h = bh % HH;
    const int q0 = blockIdx.x * 128;

    auto issue_kv = [&](int kt, int s) {
#pragma unroll
        for (int t = 0; t < 8; t++) {
            int idx = tid + t * 256;
            int a = idx >> 9, loc = idx & 511;
            int r = loc >> 3, cc = loc & 7;
            const __nv_bfloat16* gp = (a == 0) ? kh : (a == 1) ? kl
                                     : (a == 2) ? vh : vl;
            CP_ASYNC16(kvb + s * KVSTG + a * KAR + r * AROW_B + cc * 16,
                       gp + (size_t)(b * TT + kt * 64 + r) * CC + h * DHD + cc * 8);
        }
        CP_COMMIT;
    };

    // ---- preamble: Q (both arrays) + KV tile 0 ----
    {
#pragma unroll
        for (int t = 0; t < 8; t++) {
            int idx = tid + t * 256;
            int a = idx >> 10, loc = idx & 1023;
            int r = loc >> 3, cc = loc & 7;
            const __nv_bfloat16* gp = a ? ql : qh;
            CP_ASYNC16(sbase + a * QAR + r * AROW_B + cc * 16,
                       gp + (size_t)(b * TT + q0 + r) * CC + h * DHD + cc * 8);
        }
        CP_COMMIT;
    }
    issue_kv(0, 0);
    CP_WAIT0;
    __syncthreads();

    // ---- Q hi fragments persistent; lo re-loaded per tile ----
    const uint32_t qaoff = (uint32_t)((w * 16 + (lane & 15)) * AROW_B +
                                      ((lane >> 4) << 4));
    uint32_t qf_h[4][4];
#pragma unroll
    for (int ks = 0; ks < 4; ks++)
        LDSM_X4(qf_h[ks][0], qf_h[ks][1], qf_h[ks][2], qf_h[ks][3],
                sbase + qaoff + ks * 32);

    // per-lane hi/lo-combined fragment offsets (hi array for lanes 0-15, lo for 16-31)
    const uint32_t hilo = (lane >> 4) ? KAR : 0;
    const uint32_t k_lane = hilo + (uint32_t)((lane & 7) * AROW_B +
                                              (((lane >> 3) & 1) << 4));
    const uint32_t v_lane = hilo + (uint32_t)((lane & 15) * AROW_B);

    float oacc[8][4];
#pragma unroll
    for (int jd = 0; jd < 8; jd++)
#pragma unroll
        for (int e = 0; e < 4; e++) oacc[jd][e] = 0.f;
    float m0i = -INFINITY, m1i = -INFINITY, l0i = 0.f, l1i = 0.f;

    const int NT = TT / 64;
    for (int kt = 0; kt < NT; kt++) {
        if (kt + 1 < NT) {
            issue_kv(kt + 1, (kt + 1) & 1);
            CP_WAIT1;
        } else {
            CP_WAIT0;
        }
        __syncthreads();

        const uint32_t kh_b = kvb + (kt & 1) * KVSTG;      // + KAR = kl
        const uint32_t vh_b = kh_b + 2 * KAR;              // + KAR = vl

        // ---- S = Q K^T (3-term compensated) ----
        float sacc[8][4];
#pragma unroll
        for (int j = 0; j < 8; j++)
#pragma unroll
            for (int e = 0; e < 4; e++) sacc[j][e] = 0.f;

#pragma unroll
        for (int ks = 0; ks < 4; ks++) {
            uint32_t qf_l[4];
            LDSM_X4(qf_l[0], qf_l[1], qf_l[2], qf_l[3],
                    sbase + QAR + qaoff + ks * 32);
#pragma unroll
            for (int j = 0; j < 8; j++) {
                // one x4: {bh2[0],bh2[1],bl2[0],bl2[1]}
                uint32_t bh2[2], bl2[2];
                LDSM_X4(bh2[0], bh2[1], bl2[0], bl2[1],
                        kh_b + k_lane + (uint32_t)(j * 8 * AROW_B) + ks * 32);
                MMA_BF16(sacc[j], qf_h[ks], bh2);
                MMA_BF16(sacc[j], qf_h[ks], bl2);
                MMA_BF16(sacc[j], qf_l, bh2);
            }
        }

        // ---- scale + mask (mask: L1-hot global array) ----
        const float* mrow = &mask[b * TT + kt * 64];
#pragma unroll
        for (int j = 0; j < 8; j++) {
            float km0 = mrow[j * 8 + 2 * qc];
            float km1 = mrow[j * 8 + 2 * qc + 1];
            sacc[j][0] = sacc[j][0] * 0.125f + km0;
            sacc[j][1] = sacc[j][1] * 0.125f + km1;
            sacc[j][2] = sacc[j][2] * 0.125f + km0;
            sacc[j][3] = sacc[j][3] * 0.125f + km1;
        }

        // ---- online softmax ----
        float mx0 = -INFINITY, mx1 = -INFINITY;
#pragma unroll
        for (int j = 0; j < 8; j++) {
            mx0 = fmaxf(mx0, fmaxf(sacc[j][0], sacc[j][1]));
            mx1 = fmaxf(mx1, fmaxf(sacc[j][2], sacc[j][3]));
        }
        mx0 = fmaxf(mx0, __shfl_xor_sync(0xffffffffu, mx0, 1));
        mx0 = fmaxf(mx0, __shfl_xor_sync(0xffffffffu, mx0, 2));
        mx1 = fmaxf(mx1, __shfl_xor_sync(0xffffffffu, mx1, 1));
        mx1 = fmaxf(mx1, __shfl_xor_sync(0xffffffffu, mx1, 2));
        float mn0 = fmaxf(m0i, mx0), mn1 = fmaxf(m1i, mx1);
        float esc0 = __expf(m0i - mn0), esc1 = __expf(m1i - mn1);
        float rs0 = 0.f, rs1 = 0.f;
#pragma unroll
        for (int j = 0; j < 8; j++) {
            float p0 = __expf(sacc[j][0] - mn0);
            float p1 = __expf(sacc[j][1] - mn0);
            float p2 = __expf(sacc[j][2] - mn1);
            float p3 = __expf(sacc[j][3] - mn1);
            sacc[j][0] = p0; sacc[j][1] = p1; sacc[j][2] = p2; sacc[j][3] = p3;
            rs0 += p0 + p1;
            rs1 += p2 + p3;
        }
        rs0 += __shfl_xor_sync(0xffffffffu, rs0, 1);
        rs0 += __shfl_xor_sync(0xffffffffu, rs0, 2);
        rs1 += __shfl_xor_sync(0xffffffffu, rs1, 1);
        rs1 += __shfl_xor_sync(0xffffffffu, rs1, 2);
        l0i = l0i * esc0 + rs0;
        l1i = l1i * esc1 + rs1;
        m0i = mn0; m1i = mn1;
#pragma unroll
        for (int jd = 0; jd < 8; jd++) {
            oacc[jd][0] *= esc0; oacc[jd][1] *= esc0;
            oacc[jd][2] *= esc1; oacc[jd][3] *= esc1;
        }

        // ---- P -> bf16 hi/lo A fragments (register-only) ----
        uint32_t pf_h[4][4], pf_l[4][4];
#pragma unroll
        for (int ks = 0; ks < 4; ks++) {
            int j0 = 2 * ks, j1 = 2 * ks + 1;
            split2(sacc[j0][0], sacc[j0][1], pf_h[ks][0], pf_l[ks][0]);
            split2(sacc[j0][2], sacc[j0][3], pf_h[ks][1], pf_l[ks][1]);
            split2(sacc[j1][0], sacc[j1][1], pf_h[ks][2], pf_l[ks][2]);
            split2(sacc[j1][2], sacc[j1][3], pf_h[ks][3], pf_l[ks][3]);
        }

        // ---- O += P V (3-term); V hi+lo via one ldmatrix.x4.trans ----
#pragma unroll
        for (int jd = 0; jd < 8; jd++) {
#pragma unroll
            for (int ks = 0; ks < 4; ks++) {
                uint32_t bvh[2], bvl[2];
                LDSM_X4_T(bvh[0], bvh[1], bvl[0], bvl[1],
                          vh_b + v_lane + (uint32_t)(ks * 16 * AROW_B) + jd * 16);
                MMA_BF16(oacc[jd], pf_h[ks], bvh);
                MMA_BF16(oacc[jd], pf_h[ks], bvl);
                MMA_BF16(oacc[jd], pf_l[ks], bvh);
            }
        }
        __syncthreads();
    }

    // ---- epilogue: normalize + split-store ----
    float inv0 = 1.f / l0i, inv1 = 1.f / l1i;
    const int r0 = q0 + w * 16 + g;
    const size_t obase = (size_t)(b * TT + r0) * CC + h * DHD;
#pragma unroll
    for (int jd = 0; jd < 8; jd++) {
        int col = jd * 8 + 2 * qc;
        uint32_t hi, lo;
        split2(oacc[jd][0] * inv0, oacc[jd][1] * inv0, hi, lo);
        *(uint32_t*)&ph[obase + col] = hi;
        *(uint32_t*)&pl[obase + col] = lo;
        split2(oacc[jd][2] * inv1, oacc[jd][3] * inv1, hi, lo);
        *(uint32_t*)&ph[obase + 8 * CC + col] = hi;
        *(uint32_t*)&pl[obase + 8 * CC + col] = lo;
    }
}

// ---------------------------------------------------------------------------
extern "C" void kernel_launch(void* const* d_in, const int* in_sizes, int n_in,
                              void* d_out, int out_size) {
    const float* x   = (const float*)d_in[0];
    const float* wq  = (const float*)d_in[1];
    const float* bq  = (const float*)d_in[2];
    const float* wk  = (const float*)d_in[3];
    const float* bk  = (const float*)d_in[4];
    const float* wv  = (const float*)d_in[5];
    const float* bv  = (const float*)d_in[6];
    const float* wo  = (const float*)d_in[7];
    const float* bo  = (const float*)d_in[8];
    float* out = (float*)d_out;

    __nv_bfloat16 *xh, *xl, *wqh, *wql, *wkh, *wkl, *wvh, *wvl, *woh, *wol;
    __nv_bfloat16 *qh, *ql, *kh, *kl, *vh, *vl, *ph, *pl;
    float* maskp;
    cudaGetSymbolAddress((void**)&xh, g_xh);   cudaGetSymbolAddress((void**)&xl, g_xl);
    cudaGetSymbolAddress((void**)&wqh, g_wqh); cudaGetSymbolAddress((void**)&wql, g_wql);
    cudaGetSymbolAddress((void**)&wkh, g_wkh); cudaGetSymbolAddress((void**)&wkl, g_wkl);
    cudaGetSymbolAddress((void**)&wvh, g_wvh); cudaGetSymbolAddress((void**)&wvl, g_wvl);
    cudaGetSymbolAddress((void**)&woh, g_woh); cudaGetSymbolAddress((void**)&wol, g_wol);
    cudaGetSymbolAddress((void**)&qh, g_qh);   cudaGetSymbolAddress((void**)&ql, g_ql);
    cudaGetSymbolAddress((void**)&kh, g_kh);   cudaGetSymbolAddress((void**)&kl, g_kl);
    cudaGetSymbolAddress((void**)&vh, g_vh);   cudaGetSymbolAddress((void**)&vl, g_vl);
    cudaGetSymbolAddress((void**)&ph, g_ph);   cudaGetSymbolAddress((void**)&pl, g_pl);
    cudaGetSymbolAddress((void**)&maskp, g_mask);

    cudaFuncSetAttribute(gemm_bf16_tc, cudaFuncAttributeMaxDynamicSharedMemorySize,
                         GSMEM);
    cudaFuncSetAttribute(attn_tc, cudaFuncAttributeMaxDynamicSharedMemorySize,
                         ASMEM);

    // ---- fused pre-split (x + 4 weights + mask) ----
    split_all<<<(N4X + 4 * N4W + 255) / 256, 256>>>(
        x, wq, wk, wv, wo, xh, xl, wqh, wql, wkh, wkl, wvh, wvl, woh, wol, maskp);

    dim3 gblk(256);
    dim3 ggrid(CC / 128, MTOT / 128);  // (8, 32)

    gemm_bf16_tc<<<ggrid, gblk, GSMEM>>>(xh, xl, wqh, wql, bq, nullptr, qh, ql,
                                         MTOT, CC, CC, 1);
    gemm_bf16_tc<<<ggrid, gblk, GSMEM>>>(xh, xl, wkh, wkl, bk, nullptr, kh, kl,
                                         MTOT, CC, CC, 1);
    gemm_bf16_tc<<<ggrid, gblk, GSMEM>>>(xh, xl, wvh, wvl, bv, nullptr, vh, vl,
                                         MTOT, CC, CC, 1);

    dim3 agrid(TT / 128, BB * HH);  // (16, 32)
    attn_tc<<<agrid, 256, ASMEM>>>(qh, ql, kh, kl, vh, vl, maskp, ph, pl);

    gemm_bf16_tc<<<ggrid, gblk, GSMEM>>>(ph, pl, woh, wol, bo, out, nullptr, nullptr,
                                         MTOT, CC, CC, 0);
}

// round 15
// speedup vs baseline: 3.5854x; 1.0764x over previous
#include <cuda_runtime.h>
#include <cuda_bf16.h>
#include <stdint.h>
#include <math.h>

#define BB 2
#define TT 2048
#define CC 1024
#define HH 16
#define DHD 64
#define MTOT (BB*TT)

// ---- GEMM smem: 3 stages x 4 arrays x 128 rows x 64B (XOR-swizzled) ----
#define GAR_N 8192             // 128 * 64 B
#define GSTG_N (4 * GAR_N)     // 32768 B per stage
#define GSMEM_N (3 * GSTG_N)   // 98304 B

// ---- Attention smem: Q (2 arrays x 128 x 144B) + KV 2 stages x 4 arrays x 64 x 144B ----
#define AROW_B 144
#define QAR (128 * AROW_B)     // 18432
#define KAR (64 * AROW_B)      // 9216
#define KVSTG (4 * KAR)        // 36864
#define ASMEM (2 * QAR + 2 * KVSTG)  // 110592

// ---- scratch (no allocation allowed) ----
__device__ __nv_bfloat16 g_xh[MTOT * CC], g_xl[MTOT * CC];
__device__ __nv_bfloat16 g_wch[3 * CC * CC], g_wcl[3 * CC * CC];   // wq|wk|wv
__device__ __nv_bfloat16 g_woh[CC * CC], g_wol[CC * CC];
__device__ __nv_bfloat16 g_qkvh[MTOT * 3 * CC], g_qkvl[MTOT * 3 * CC];
__device__ __nv_bfloat16 g_ph[MTOT * CC], g_pl[MTOT * CC];
__device__ float g_bias3[3 * CC];
__device__ float g_mask[MTOT];

__device__ __forceinline__ uint32_t smem_u32(const void* p) {
    return (uint32_t)__cvta_generic_to_shared(p);
}

#define LDSM_X4(r0, r1, r2, r3, addr)                                          \
    asm volatile("ldmatrix.sync.aligned.m8n8.x4.shared.b16 {%0,%1,%2,%3}, [%4];" \
                 : "=r"(r0), "=r"(r1), "=r"(r2), "=r"(r3) : "r"(addr))
#define LDSM_X4_T(r0, r1, r2, r3, addr)                                        \
    asm volatile("ldmatrix.sync.aligned.m8n8.x4.trans.shared.b16 {%0,%1,%2,%3}, [%4];" \
                 : "=r"(r0), "=r"(r1), "=r"(r2), "=r"(r3) : "r"(addr))

#define MMA_BF16(d, a, b)                                                      \
    asm volatile("mma.sync.aligned.m16n8k16.row.col.f32.bf16.bf16.f32 "        \
                 "{%0,%1,%2,%3}, {%4,%5,%6,%7}, {%8,%9}, {%0,%1,%2,%3};"       \
                 : "+f"((d)[0]), "+f"((d)[1]), "+f"((d)[2]), "+f"((d)[3])      \
                 : "r"((a)[0]), "r"((a)[1]), "r"((a)[2]), "r"((a)[3]),         \
                   "r"((b)[0]), "r"((b)[1]))

#define CP_ASYNC16(saddr, gaddr)                                               \
    asm volatile("cp.async.cg.shared.global [%0], [%1], 16;"                   \
                 :: "r"(saddr), "l"(gaddr))
#define CP_COMMIT  asm volatile("cp.async.commit_group;")
#define CP_WAIT0   asm volatile("cp.async.wait_group 0;")
#define CP_WAIT1   asm volatile("cp.async.wait_group 1;")

// split fp32 pair -> packed bf16 hi + packed bf16 residual
__device__ __forceinline__ void split2(float a, float b, uint32_t& hi, uint32_t& lo) {
    __nv_bfloat162 h = __float22bfloat162_rn(make_float2(a, b));
    float2 hf = __bfloat1622float2(h);
    __nv_bfloat162 l = __float22bfloat162_rn(make_float2(a - hf.x, b - hf.y));
    hi = *reinterpret_cast<uint32_t*>(&h);
    lo = *reinterpret_cast<uint32_t*>(&l);
}

// ---------------------------------------------------------------------------
// fused preamble: split x into xh/xl; wq|wk|wv into combined wch/wcl; wo into
// woh/wol; concat biases; build pad mask.
// jr = read index into source array; jw = write index into destination.
// ---------------------------------------------------------------------------
#define N4X (MTOT * CC / 4)         // 1048576
#define N4W (CC * CC / 4)           // 262144
__global__ void split_all(const float* __restrict__ x,
                          const float* __restrict__ wq, const float* __restrict__ wk,
                          const float* __restrict__ wv, const float* __restrict__ wo,
                          const float* __restrict__ bq, const float* __restrict__ bk,
                          const float* __restrict__ bv,
                          __nv_bfloat16* __restrict__ xh, __nv_bfloat16* __restrict__ xl,
                          __nv_bfloat16* __restrict__ wch, __nv_bfloat16* __restrict__ wcl,
                          __nv_bfloat16* __restrict__ woh, __nv_bfloat16* __restrict__ wol,
                          float* __restrict__ bias3, float* __restrict__ mask) {
    int i = blockIdx.x * blockDim.x + threadIdx.x;
    const float* in;
    __nv_bfloat16 *oh, *ol;
    int jr, jw;
    if (i < N4X) {
        in = x; oh = xh; ol = xl; jr = i; jw = i;
    } else {
        int t = i - N4X;
        int w = t >> 18;          // /N4W
        jr = t & (N4W - 1);       // local float4 index into the source weight
        if (w == 0)      { in = wq; oh = wch; ol = wcl; jw = jr; }
        else if (w == 1) { in = wk; oh = wch; ol = wcl; jw = jr + N4W; }
        else if (w == 2) { in = wv; oh = wch; ol = wcl; jw = jr + 2 * N4W; }
        else             { in = wo; oh = woh; ol = wol; jw = jr; }
    }
    float4 v = ((const float4*)in)[jr];
    uint32_t h01, l01, h23, l23;
    split2(v.x, v.y, h01, l01);
    split2(v.z, v.w, h23, l23);
    ((uint32_t*)oh)[jw * 2] = h01;
    ((uint32_t*)oh)[jw * 2 + 1] = h23;
    ((uint32_t*)ol)[jw * 2] = l01;
    ((uint32_t*)ol)[jw * 2 + 1] = l23;
    if (i < MTOT) mask[i] = (x[(size_t)i * CC] != 0.0f) ? 0.f : -INFINITY;
    if (i < 3 * CC)
        bias3[i] = (i < CC) ? bq[i] : (i < 2 * CC) ? bk[i - CC] : bv[i - 2 * CC];
}

// ---------------------------------------------------------------------------
// bf16-input NT GEMM, 3-term compensated, 3-stage cp.async, ONE sync/iter.
// Swizzled 64B smem rows: chunk' = chunk ^ ((row>>1)&3).
// ---------------------------------------------------------------------------
__global__ __launch_bounds__(256, 2) void gemm_bf16_tc(
    const __nv_bfloat16* __restrict__ Ah, const __nv_bfloat16* __restrict__ Al,
    const __nv_bfloat16* __restrict__ Bh, const __nv_bfloat16* __restrict__ Bl,
    const float* __restrict__ bias, float* __restrict__ outf,
    __nv_bfloat16* __restrict__ outh, __nv_bfloat16* __restrict__ outl,
    int M, int N, int K, int out_split) {
    extern __shared__ char sgc[];
    const uint32_t sbase = smem_u32(sgc);
    const int tid = threadIdx.x;
    const int wid = tid >> 5, lane = tid & 31;
    const int warp_m = wid >> 2, warp_n = wid & 3;
    const int m0 = blockIdx.y * 128, n0 = blockIdx.x * 128;

    float acc[4][4][4];
#pragma unroll
    for (int mt = 0; mt < 4; mt++)
#pragma unroll
        for (int nt = 0; nt < 4; nt++)
#pragma unroll
            for (int e = 0; e < 4; e++) acc[mt][nt][e] = 0.f;

    // swizzled ldmatrix offsets
    uint32_t a_off[4][2], b_off[2][2];
#pragma unroll
    for (int mt = 0; mt < 4; mt++)
#pragma unroll
        for (int ks = 0; ks < 2; ks++) {
            int row = warp_m * 64 + mt * 16 + (lane & 15);
            int c = ks * 2 + (lane >> 4);
            a_off[mt][ks] = (uint32_t)(row * 64 + ((c ^ ((row >> 1) & 3)) << 4));
        }
#pragma unroll
    for (int p = 0; p < 2; p++)
#pragma unroll
        for (int ks = 0; ks < 2; ks++) {
            int row = warp_n * 32 + (2 * p + (lane >> 4)) * 8 + (lane & 7);
            int c = ks * 2 + ((lane >> 3) & 1);
            b_off[p][ks] = (uint32_t)(row * 64 + ((c ^ ((row >> 1) & 3)) << 4));
        }

    auto issue = [&](int k0, int s) {
#pragma unroll
        for (int t = 0; t < 8; t++) {
            int idx = tid + t * 256;
            int a = idx >> 9, loc = idx & 511;
            int r = loc >> 2, cc = loc & 3;
            const __nv_bfloat16* gp = (a == 0) ? Ah : (a == 1) ? Al
                                     : (a == 2) ? Bh : Bl;
            int row = ((a < 2) ? m0 : n0) + r;
            CP_ASYNC16(sbase + s * GSTG_N + a * GAR_N + r * 64 +
                           ((cc ^ ((r >> 1) & 3)) << 4),
                       gp + (size_t)row * K + k0 + cc * 8);
        }
        CP_COMMIT;
    };

    const int NIT = K / 32;
    issue(0, 0);
    issue(32, 1);
    for (int it = 0; it < NIT; it++) {
        if (it + 1 < NIT) { CP_WAIT1; } else { CP_WAIT0; }
        __syncthreads();
        if (it + 2 < NIT) issue((it + 2) * 32, (it + 2) % 3);

        const uint32_t stg = sbase + (it % 3) * GSTG_N;
#pragma unroll
        for (int term = 0; term < 3; term++) {
            uint32_t abase = stg + ((term == 2) ? GAR_N : 0);
            uint32_t bbase = stg + 2 * GAR_N + ((term == 1) ? GAR_N : 0);
#pragma unroll
            for (int ks = 0; ks < 2; ks++) {
                uint32_t af[4][4], bf[4][2];
#pragma unroll
                for (int mt = 0; mt < 4; mt++)
                    LDSM_X4(af[mt][0], af[mt][1], af[mt][2], af[mt][3],
                            abase + a_off[mt][ks]);
#pragma unroll
                for (int p = 0; p < 2; p++)
                    LDSM_X4(bf[2 * p][0], bf[2 * p][1], bf[2 * p + 1][0],
                            bf[2 * p + 1][1], bbase + b_off[p][ks]);
#pragma unroll
                for (int mt = 0; mt < 4; mt++)
#pragma unroll
                    for (int nt = 0; nt < 4; nt++)
                        MMA_BF16(acc[mt][nt], af[mt], bf[nt]);
            }
        }
    }

    const int g = lane >> 2, c = lane & 3;
#pragma unroll
    for (int nt = 0; nt < 4; nt++) {
        int col = n0 + warp_n * 32 + nt * 8 + c * 2;
        float b0 = bias[col], b1 = bias[col + 1];
#pragma unroll
        for (int mt = 0; mt < 4; mt++) {
            int row = m0 + warp_m * 64 + mt * 16 + g;
            float v00 = acc[mt][nt][0] + b0, v01 = acc[mt][nt][1] + b1;
            float v10 = acc[mt][nt][2] + b0, v11 = acc[mt][nt][3] + b1;
            if (out_split) {
                uint32_t hi, lo;
                split2(v00, v01, hi, lo);
                *(uint32_t*)&outh[(size_t)row * N + col] = hi;
                *(uint32_t*)&outl[(size_t)row * N + col] = lo;
                split2(v10, v11, hi, lo);
                *(uint32_t*)&outh[(size_t)(row + 8) * N + col] = hi;
                *(uint32_t*)&outl[(size_t)(row + 8) * N + col] = lo;
            } else {
                *(float2*)&outf[(size_t)row * N + col] = make_float2(v00, v01);
                *(float2*)&outf[(size_t)(row + 8) * N + col] = make_float2(v10, v11);
            }
        }
    }
}

// ---------------------------------------------------------------------------
// Tensor-core flash attention (qs = row stride of q/k/v arrays in elements).
// ---------------------------------------------------------------------------
__global__ __launch_bounds__(256, 2) void attn_tc(
    const __nv_bfloat16* __restrict__ qh, const __nv_bfloat16* __restrict__ ql,
    const __nv_bfloat16* __restrict__ kh, const __nv_bfloat16* __restrict__ kl,
    const __nv_bfloat16* __restrict__ vh, const __nv_bfloat16* __restrict__ vl,
    const float* __restrict__ mask,
    __nv_bfloat16* __restrict__ ph, __nv_bfloat16* __restrict__ pl, int qs) {
    extern __shared__ char sac[];
    const uint32_t sbase = smem_u32(sac);
    const uint32_t kvb = sbase + 2 * QAR;

    const int tid = threadIdx.x;
    const int w = tid >> 5, lane = tid & 31;
    const int g = lane >> 2, qc = lane & 3;
    const int bh = blockIdx.y;
    const int b = bh / HH, h = bh % HH;
    const int q0 = blockIdx.x * 128;

    auto issue_kv = [&](int kt, int s) {
#pragma unroll
        for (int t = 0; t < 8; t++) {
            int idx = tid + t * 256;
            int a = idx >> 9, loc = idx & 511;
            int r = loc >> 3, cc = loc & 7;
            const __nv_bfloat16* gp = (a == 0) ? kh : (a == 1) ? kl
                                     : (a == 2) ? vh : vl;
            CP_ASYNC16(kvb + s * KVSTG + a * KAR + r * AROW_B + cc * 16,
                       gp + (size_t)(b * TT + kt * 64 + r) * qs + h * DHD + cc * 8);
        }
        CP_COMMIT;
    };

    {
#pragma unroll
        for (int t = 0; t < 8; t++) {
            int idx = tid + t * 256;
            int a = idx >> 10, loc = idx & 1023;
            int r = loc >> 3, cc = loc & 7;
            const __nv_bfloat16* gp = a ? ql : qh;
            CP_ASYNC16(sbase + a * QAR + r * AROW_B + cc * 16,
                       gp + (size_t)(b * TT + q0 + r) * qs + h * DHD + cc * 8);
        }
        CP_COMMIT;
    }
    issue_kv(0, 0);
    CP_WAIT0;
    __syncthreads();

    const uint32_t qaoff = (uint32_t)((w * 16 + (lane & 15)) * AROW_B +
                                      ((lane >> 4) << 4));
    uint32_t qf_h[4][4];
#pragma unroll
    for (int ks = 0; ks < 4; ks++)
        LDSM_X4(qf_h[ks][0], qf_h[ks][1], qf_h[ks][2], qf_h[ks][3],
                sbase + qaoff + ks * 32);

    const uint32_t hilo = (lane >> 4) ? KAR : 0;
    const uint32_t k_lane = hilo + (uint32_t)((lane & 7) * AROW_B +
                                              (((lane >> 3) & 1) << 4));
    const uint32_t v_lane = hilo + (uint32_t)((lane & 15) * AROW_B);

    float oacc[8][4];
#pragma unroll
    for (int jd = 0; jd < 8; jd++)
#pragma unroll
        for (int e = 0; e < 4; e++) oacc[jd][e] = 0.f;
    float m0i = -INFINITY, m1i = -INFINITY, l0i = 0.f, l1i = 0.f;

    const int NT = TT / 64;
    for (int kt = 0; kt < NT; kt++) {
        if (kt + 1 < NT) {
            issue_kv(kt + 1, (kt + 1) & 1);
            CP_WAIT1;
        } else {
            CP_WAIT0;
        }
        __syncthreads();

        const uint32_t kh_b = kvb + (kt & 1) * KVSTG;
        const uint32_t vh_b = kh_b + 2 * KAR;

        float sacc[8][4];
#pragma unroll
        for (int j = 0; j < 8; j++)
#pragma unroll
            for (int e = 0; e < 4; e++) sacc[j][e] = 0.f;

#pragma unroll
        for (int ks = 0; ks < 4; ks++) {
            uint32_t qf_l[4];
            LDSM_X4(qf_l[0], qf_l[1], qf_l[2], qf_l[3],
                    sbase + QAR + qaoff + ks * 32);
#pragma unroll
            for (int j = 0; j < 8; j++) {
                uint32_t bh2[2], bl2[2];
                LDSM_X4(bh2[0], bh2[1], bl2[0], bl2[1],
                        kh_b + k_lane + (uint32_t)(j * 8 * AROW_B) + ks * 32);
                MMA_BF16(sacc[j], qf_h[ks], bh2);
                MMA_BF16(sacc[j], qf_h[ks], bl2);
                MMA_BF16(sacc[j], qf_l, bh2);
            }
        }

        const float* mrow = &mask[b * TT + kt * 64];
#pragma unroll
        for (int j = 0; j < 8; j++) {
            float km0 = mrow[j * 8 + 2 * qc];
            float km1 = mrow[j * 8 + 2 * qc + 1];
            sacc[j][0] = sacc[j][0] * 0.125f + km0;
            sacc[j][1] = sacc[j][1] * 0.125f + km1;
            sacc[j][2] = sacc[j][2] * 0.125f + km0;
            sacc[j][3] = sacc[j][3] * 0.125f + km1;
        }

        float mx0 = -INFINITY, mx1 = -INFINITY;
#pragma unroll
        for (int j = 0; j < 8; j++) {
            mx0 = fmaxf(mx0, fmaxf(sacc[j][0], sacc[j][1]));
            mx1 = fmaxf(mx1, fmaxf(sacc[j][2], sacc[j][3]));
        }
        mx0 = fmaxf(mx0, __shfl_xor_sync(0xffffffffu, mx0, 1));
        mx0 = fmaxf(mx0, __shfl_xor_sync(0xffffffffu, mx0, 2));
        mx1 = fmaxf(mx1, __shfl_xor_sync(0xffffffffu, mx1, 1));
        mx1 = fmaxf(mx1, __shfl_xor_sync(0xffffffffu, mx1, 2));
        float mn0 = fmaxf(m0i, mx0), mn1 = fmaxf(m1i, mx1);
        float esc0 = __expf(m0i - mn0), esc1 = __expf(m1i - mn1);
        float rs0 = 0.f, rs1 = 0.f;
#pragma unroll
        for (int j = 0; j < 8; j++) {
            float p0 = __expf(sacc[j][0] - mn0);
            float p1 = __expf(sacc[j][1] - mn0);
            float p2 = __expf(sacc[j][2] - mn1);
            float p3 = __expf(sacc[j][3] - mn1);
            sacc[j][0] = p0; sacc[j][1] = p1; sacc[j][2] = p2; sacc[j][3] = p3;
            rs0 += p0 + p1;
            rs1 += p2 + p3;
        }
        rs0 += __shfl_xor_sync(0xffffffffu, rs0, 1);
        rs0 += __shfl_xor_sync(0xffffffffu, rs0, 2);
        rs1 += __shfl_xor_sync(0xffffffffu, rs1, 1);
        rs1 += __shfl_xor_sync(0xffffffffu, rs1, 2);
        l0i = l0i * esc0 + rs0;
        l1i = l1i * esc1 + rs1;
        m0i = mn0; m1i = mn1;
#pragma unroll
        for (int jd = 0; jd < 8; jd++) {
            oacc[jd][0] *= esc0; oacc[jd][1] *= esc0;
            oacc[jd][2] *= esc1; oacc[jd][3] *= esc1;
        }

        uint32_t pf_h[4][4], pf_l[4][4];
#pragma unroll
        for (int ks = 0; ks < 4; ks++) {
            int j0 = 2 * ks, j1 = 2 * ks + 1;
            split2(sacc[j0][0], sacc[j0][1], pf_h[ks][0], pf_l[ks][0]);
            split2(sacc[j0][2], sacc[j0][3], pf_h[ks][1], pf_l[ks][1]);
            split2(sacc[j1][0], sacc[j1][1], pf_h[ks][2], pf_l[ks][2]);
            split2(sacc[j1][2], sacc[j1][3], pf_h[ks][3], pf_l[ks][3]);
        }

#pragma unroll
        for (int jd = 0; jd < 8; jd++) {
#pragma unroll
            for (int ks = 0; ks < 4; ks++) {
                uint32_t bvh[2], bvl[2];
                LDSM_X4_T(bvh[0], bvh[1], bvl[0], bvl[1],
                          vh_b + v_lane + (uint32_t)(ks * 16 * AROW_B) + jd * 16);
                MMA_BF16(oacc[jd], pf_h[ks], bvh);
                MMA_BF16(oacc[jd], pf_h[ks], bvl);
                MMA_BF16(oacc[jd], pf_l[ks], bvh);
            }
        }
        __syncthreads();
    }

    float inv0 = 1.f / l0i, inv1 = 1.f / l1i;
    const int r0 = q0 + w * 16 + g;
    const size_t obase = (size_t)(b * TT + r0) * CC + h * DHD;
#pragma unroll
    for (int jd = 0; jd < 8; jd++) {
        int col = jd * 8 + 2 * qc;
        uint32_t hi, lo;
        split2(oacc[jd][0] * inv0, oacc[jd][1] * inv0, hi, lo);
        *(uint32_t*)&ph[obase + col] = hi;
        *(uint32_t*)&pl[obase + col] = lo;
        split2(oacc[jd][2] * inv1, oacc[jd][3] * inv1, hi, lo);
        *(uint32_t*)&ph[obase + 8 * CC + col] = hi;
        *(uint32_t*)&pl[obase + 8 * CC + col] = lo;
    }
}

// ---------------------------------------------------------------------------
extern "C" void kernel_launch(void* const* d_in, const int* in_sizes, int n_in,
                              void* d_out, int out_size) {
    const float* x   = (const float*)d_in[0];
    const float* wq  = (const float*)d_in[1];
    const float* bq  = (const float*)d_in[2];
    const float* wk  = (const float*)d_in[3];
    const float* bk  = (const float*)d_in[4];
    const float* wv  = (const float*)d_in[5];
    const float* bv  = (const float*)d_in[6];
    const float* wo  = (const float*)d_in[7];
    const float* bo  = (const float*)d_in[8];
    float* out = (float*)d_out;

    __nv_bfloat16 *xh, *xl, *wch, *wcl, *woh, *wol, *qkvh, *qkvl, *ph, *pl;
    float *bias3, *maskp;
    cudaGetSymbolAddress((void**)&xh, g_xh);     cudaGetSymbolAddress((void**)&xl, g_xl);
    cudaGetSymbolAddress((void**)&wch, g_wch);   cudaGetSymbolAddress((void**)&wcl, g_wcl);
    cudaGetSymbolAddress((void**)&woh, g_woh);   cudaGetSymbolAddress((void**)&wol, g_wol);
    cudaGetSymbolAddress((void**)&qkvh, g_qkvh); cudaGetSymbolAddress((void**)&qkvl, g_qkvl);
    cudaGetSymbolAddress((void**)&ph, g_ph);     cudaGetSymbolAddress((void**)&pl, g_pl);
    cudaGetSymbolAddress((void**)&bias3, g_bias3);
    cudaGetSymbolAddress((void**)&maskp, g_mask);

    cudaFuncSetAttribute(gemm_bf16_tc, cudaFuncAttributeMaxDynamicSharedMemorySize,
                         GSMEM_N);
    cudaFuncSetAttribute(attn_tc, cudaFuncAttributeMaxDynamicSharedMemorySize,
                         ASMEM);

    split_all<<<(N4X + 4 * N4W + 255) / 256, 256>>>(
        x, wq, wk, wv, wo, bq, bk, bv, xh, xl, wch, wcl, woh, wol, bias3, maskp);

    // fused QKV: [4096,1024] x [3072,1024]^T -> split bf16 [4096,3072]
    gemm_bf16_tc<<<dim3(3 * CC / 128, MTOT / 128), 256, GSMEM_N>>>(
        xh, xl, wch, wcl, bias3, nullptr, qkvh, qkvl, MTOT, 3 * CC, CC, 1);

    attn_tc<<<dim3(TT / 128, BB * HH), 256, ASMEM>>>(
        qkvh, qkvl, qkvh + CC, qkvl + CC, qkvh + 2 * CC, qkvl + 2 * CC,
        maskp, ph, pl, 3 * CC);

    gemm_bf16_tc<<<dim3(CC / 128, MTOT / 128), 256, GSMEM_N>>>(
        ph, pl, woh, wol, bo, out, nullptr, nullptr, MTOT, CC, CC, 0);
}